// round 4
// baseline (speedup 1.0000x reference)
#include <cuda_runtime.h>
#include <math.h>

#define Bz   2
#define Tt   1024
#define Dd   512
#define NHh  8
#define HDd  64
#define Ll   4
#define Ee   8
#define Hh   2048
#define NT   (Bz*Tt)   // 2048 tokens

// ---------------- scratch (device globals; no allocation allowed) ----------
__device__ float g_h   [NT*Dd];          // residual stream
__device__ float g_xn  [NT*Dd];          // normed activations
__device__ float g_qkv [NT*3*Dd];
__device__ float g_q   [NT*Dd];
__device__ float g_k   [NT*Dd];
__device__ float g_v   [NT*Dd];
__device__ float g_attn[NT*Dd];
__device__ float g_hbuf[(size_t)Ee*NT*Hh];   // expert/dense hidden (134MB)
__device__ float g_yslot[2*NT*Dd];           // per (token,slot) expert output
__device__ int   g_cnt [Ee];
__device__ int   g_tok [Ee*NT];              // packed token*2+slot
__device__ float g_wt  [Ee*NT];

// ---------------- rmsnorm ---------------------------------------------------
__global__ void rmsnorm_kernel(const float* __restrict__ in,
                               const float* __restrict__ w,
                               float* __restrict__ out) {
    int row = blockIdx.x;
    const float* x = in + (size_t)row*Dd;
    float s = 0.f;
    for (int j = threadIdx.x; j < Dd; j += 256) { float v = x[j]; s += v*v; }
    __shared__ float red[8];
    for (int o = 16; o; o >>= 1) s += __shfl_xor_sync(0xffffffffu, s, o);
    if ((threadIdx.x & 31) == 0) red[threadIdx.x >> 5] = s;
    __syncthreads();
    if (threadIdx.x < 8) {
        float v = red[threadIdx.x];
        for (int o = 4; o; o >>= 1) v += __shfl_xor_sync(0xffu, v, o);
        if (threadIdx.x == 0) red[0] = v;
    }
    __syncthreads();
    float rms = rsqrtf(red[0] / (float)Dd + 1e-5f);
    for (int j = threadIdx.x; j < Dd; j += 256)
        out[(size_t)row*Dd + j] = w[j] * x[j] * rms;
}

// ---------------- generic C = A @ W^T (+res) --------------------------------
// A: [N,K], W: [M,K] row-major. Tile 64x64, K-step 16, 256 threads, 4x4 micro.
__global__ void gemm_nt_kernel(const float* __restrict__ A,
                               const float* __restrict__ W,
                               float* __restrict__ C,
                               const float* __restrict__ Res,
                               int M, int K) {
    __shared__ float As[64][17];
    __shared__ float Ws[64][17];
    int t  = threadIdx.x;
    int tx = t & 15, ty = t >> 4;
    int rb = blockIdx.y * 64, cb = blockIdx.x * 64;
    int lr = t >> 2, lk = (t & 3) << 2;
    float acc[4][4] = {};
    for (int k0 = 0; k0 < K; k0 += 16) {
        float4 av = *(const float4*)(A + (size_t)(rb + lr)*K + k0 + lk);
        float4 wv = *(const float4*)(W + (size_t)(cb + lr)*K + k0 + lk);
        As[lr][lk+0]=av.x; As[lr][lk+1]=av.y; As[lr][lk+2]=av.z; As[lr][lk+3]=av.w;
        Ws[lr][lk+0]=wv.x; Ws[lr][lk+1]=wv.y; Ws[lr][lk+2]=wv.z; Ws[lr][lk+3]=wv.w;
        __syncthreads();
#pragma unroll
        for (int kk = 0; kk < 16; kk++) {
            float a[4], b[4];
#pragma unroll
            for (int i = 0; i < 4; i++) a[i] = As[ty*4+i][kk];
#pragma unroll
            for (int j = 0; j < 4; j++) b[j] = Ws[tx*4+j][kk];
#pragma unroll
            for (int i = 0; i < 4; i++)
#pragma unroll
                for (int j = 0; j < 4; j++) acc[i][j] += a[i]*b[j];
        }
        __syncthreads();
    }
#pragma unroll
    for (int i = 0; i < 4; i++)
#pragma unroll
        for (int j = 0; j < 4; j++) {
            size_t idx = (size_t)(rb + ty*4 + i)*M + cb + tx*4 + j;
            float v = acc[i][j];
            if (Res) v += Res[idx];
            C[idx] = v;
        }
}

// ---------------- qkv split + RoPE ------------------------------------------
__global__ void split_rope_kernel(const float* __restrict__ qkv,
                                  float* __restrict__ Q,
                                  float* __restrict__ K,
                                  float* __restrict__ V) {
    int idx = blockIdx.x*256 + threadIdx.x;
    if (idx >= NT*NHh*32) return;
    int d  = idx & 31;
    int h  = (idx >> 5) & 7;
    int bt = idx >> 8;            // b*1024 + t
    int tt = bt & (Tt-1);
    int b  = bt >> 10;
    // inv_freq = 10000^(-d/32)
    float inv = expf(-(float)d * 0.28782313662425575f);   // ln(1e4)/32
    float sn, cs;
    sincosf((float)tt * inv, &sn, &cs);
    size_t bi = (size_t)bt*1536 + h*64 + d;
    float q1 = qkv[bi],        q2 = qkv[bi+32];
    float k1 = qkv[bi+512],    k2 = qkv[bi+544];
    float v1 = qkv[bi+1024],   v2 = qkv[bi+1056];
    int bh = b*NHh + h;
    size_t oi = ((size_t)bh*Tt + tt)*64 + d;
    Q[oi]    = q1*cs - q2*sn;  Q[oi+32] = q1*sn + q2*cs;
    K[oi]    = k1*cs - k2*sn;  K[oi+32] = k1*sn + k2*cs;
    V[oi]    = v1;             V[oi+32] = v2;
}

// ---------------- flash attention (causal, HD=64) ---------------------------
// grid: (qt=16, bh=16), block 256. dynamic smem = 3 * 64*65*4 bytes.
__global__ void attn_kernel(const float* __restrict__ Q,
                            const float* __restrict__ K,
                            const float* __restrict__ V,
                            float* __restrict__ Out) {
    extern __shared__ float sm[];
    float* Qs  = sm;             // 64x65
    float* KPs = sm + 64*65;     // K tile, reused as P tile
    float* Vs  = sm + 2*64*65;
    int qt = blockIdx.x, bh = blockIdx.y;
    int t = threadIdx.x;
    int rg = t >> 4, cg = t & 15;          // 4 rows x 4 cols per thread
    const float* Qb = Q + (size_t)bh*Tt*64;
    const float* Kb = K + (size_t)bh*Tt*64;
    const float* Vb = V + (size_t)bh*Tt*64;
#pragma unroll
    for (int i = 0; i < 4; i++) {
        int idx = t + i*256;
        int r = idx >> 4, c4 = (idx & 15) << 2;
        float4 v4 = *(const float4*)(Qb + (size_t)(qt*64 + r)*64 + c4);
        Qs[r*65+c4+0]=v4.x*0.125f; Qs[r*65+c4+1]=v4.y*0.125f;
        Qs[r*65+c4+2]=v4.z*0.125f; Qs[r*65+c4+3]=v4.w*0.125f;
    }
    float m[4] = {-1e30f,-1e30f,-1e30f,-1e30f};
    float l[4] = {0.f,0.f,0.f,0.f};
    float O[4][4] = {};
    for (int kt = 0; kt <= qt; kt++) {
        __syncthreads();
#pragma unroll
        for (int i = 0; i < 4; i++) {
            int idx = t + i*256;
            int r = idx >> 4, c4 = (idx & 15) << 2;
            float4 kv = *(const float4*)(Kb + (size_t)(kt*64 + r)*64 + c4);
            KPs[r*65+c4+0]=kv.x; KPs[r*65+c4+1]=kv.y; KPs[r*65+c4+2]=kv.z; KPs[r*65+c4+3]=kv.w;
            float4 vv = *(const float4*)(Vb + (size_t)(kt*64 + r)*64 + c4);
            Vs[r*65+c4+0]=vv.x; Vs[r*65+c4+1]=vv.y; Vs[r*65+c4+2]=vv.z; Vs[r*65+c4+3]=vv.w;
        }
        __syncthreads();
        float s[4][4] = {};
#pragma unroll
        for (int kk = 0; kk < 64; kk++) {
            float a[4], b[4];
#pragma unroll
            for (int i = 0; i < 4; i++) a[i] = Qs[(rg*4+i)*65 + kk];
#pragma unroll
            for (int j = 0; j < 4; j++) b[j] = KPs[(cg*4+j)*65 + kk];
#pragma unroll
            for (int i = 0; i < 4; i++)
#pragma unroll
                for (int j = 0; j < 4; j++) s[i][j] += a[i]*b[j];
        }
        if (kt == qt) {
#pragma unroll
            for (int i = 0; i < 4; i++)
#pragma unroll
                for (int j = 0; j < 4; j++)
                    if (cg*4+j > rg*4+i) s[i][j] = -1e30f;
        }
#pragma unroll
        for (int i = 0; i < 4; i++) {
            float rm = fmaxf(fmaxf(s[i][0], s[i][1]), fmaxf(s[i][2], s[i][3]));
            for (int o = 8; o; o >>= 1) rm = fmaxf(rm, __shfl_xor_sync(0xffffffffu, rm, o));
            float nm = fmaxf(m[i], rm);
            float f  = expf(m[i] - nm);
            float rs = 0.f;
#pragma unroll
            for (int j = 0; j < 4; j++) { s[i][j] = expf(s[i][j] - nm); rs += s[i][j]; }
            for (int o = 8; o; o >>= 1) rs += __shfl_xor_sync(0xffffffffu, rs, o);
            l[i] = l[i]*f + rs;
            m[i] = nm;
#pragma unroll
            for (int j = 0; j < 4; j++) O[i][j] *= f;
        }
        __syncthreads();   // done reading KPs as K
#pragma unroll
        for (int i = 0; i < 4; i++)
#pragma unroll
            for (int j = 0; j < 4; j++)
                KPs[(rg*4+i)*65 + cg*4+j] = s[i][j];
        __syncthreads();
#pragma unroll
        for (int jk = 0; jk < 64; jk++) {
            float p[4], v[4];
#pragma unroll
            for (int i = 0; i < 4; i++) p[i] = KPs[(rg*4+i)*65 + jk];
#pragma unroll
            for (int j = 0; j < 4; j++) v[j] = Vs[jk*65 + cg*4+j];
#pragma unroll
            for (int i = 0; i < 4; i++)
#pragma unroll
                for (int j = 0; j < 4; j++) O[i][j] += p[i]*v[j];
        }
    }
    int b = bh >> 3, hh = bh & 7;
#pragma unroll
    for (int i = 0; i < 4; i++) {
        float invl = 1.f / l[i];
        int qrow = qt*64 + rg*4 + i;
#pragma unroll
        for (int j = 0; j < 4; j++)
            Out[((size_t)(b*Tt + qrow))*Dd + hh*64 + cg*4 + j] = O[i][j]*invl;
    }
}

// ---------------- router (logits + top-2 + softmax + scatter) ---------------
__global__ void router_kernel(const float* __restrict__ X,
                              const float* __restrict__ RW,
                              int* __restrict__ cnt,
                              int* __restrict__ tok,
                              float* __restrict__ wt) {
    int gtid = blockIdx.x*blockDim.x + threadIdx.x;
    int warp = gtid >> 5, lane = gtid & 31;
    if (warp >= NT) return;
    const float* xr = X + (size_t)warp*Dd;
    float lg[Ee];
#pragma unroll
    for (int e = 0; e < Ee; e++) {
        const float* w = RW + (size_t)e*Dd;
        float s = 0.f;
        for (int j = lane; j < Dd; j += 32) s += xr[j]*w[j];
        for (int o = 16; o; o >>= 1) s += __shfl_xor_sync(0xffffffffu, s, o);
        lg[e] = s;
    }
    if (lane == 0) {
        int i0 = 0; float v0 = lg[0];
#pragma unroll
        for (int e = 1; e < Ee; e++) if (lg[e] > v0) { v0 = lg[e]; i0 = e; }
        int i1 = -1; float v1 = -3.4e38f;
#pragma unroll
        for (int e = 0; e < Ee; e++) if (e != i0 && lg[e] > v1) { v1 = lg[e]; i1 = e; }
        float e1 = expf(v1 - v0);
        float w0 = 1.f/(1.f + e1), w1 = e1/(1.f + e1);
        int p0 = atomicAdd(&cnt[i0], 1);
        tok[i0*NT + p0] = warp*2;     wt[i0*NT + p0] = w0;
        int p1 = atomicAdd(&cnt[i1], 1);
        tok[i1*NT + p1] = warp*2 + 1; wt[i1*NT + p1] = w1;
    }
}

// ---------------- fused FFN up: h = silu(X@W1^T) * (X@W3^T) -----------------
template<bool GROUPED>
__global__ void ffn_up_kernel(const float* __restrict__ X,
                              const float* __restrict__ W1,
                              const float* __restrict__ W3,
                              float* __restrict__ Hbuf,
                              const int* __restrict__ tok,
                              const int* __restrict__ cnt) {
    int e = GROUPED ? blockIdx.z : 0;
    int n = GROUPED ? cnt[e] : NT;
    int rb = blockIdx.y * 64;
    if (rb >= n) return;
    __shared__ float As[64][17], B1s[64][17], B3s[64][17];
    int t = threadIdx.x, tx = t & 15, ty = t >> 4;
    int cb = blockIdx.x * 64;
    int lr = t >> 2, lk = (t & 3) << 2;
    int ar = rb + lr; if (ar > n-1) ar = n-1;
    int xrow = GROUPED ? (tok[e*NT + ar] >> 1) : ar;
    const float* xr = X  + (size_t)xrow*Dd;
    const float* w1 = W1 + (size_t)e*Hh*Dd + (size_t)(cb + lr)*Dd;
    const float* w3 = W3 + (size_t)e*Hh*Dd + (size_t)(cb + lr)*Dd;
    float a1[4][4] = {}, a3[4][4] = {};
    for (int k0 = 0; k0 < Dd; k0 += 16) {
        float4 xv  = *(const float4*)(xr + k0 + lk);
        float4 w1v = *(const float4*)(w1 + k0 + lk);
        float4 w3v = *(const float4*)(w3 + k0 + lk);
        As [lr][lk+0]=xv.x;  As [lr][lk+1]=xv.y;  As [lr][lk+2]=xv.z;  As [lr][lk+3]=xv.w;
        B1s[lr][lk+0]=w1v.x; B1s[lr][lk+1]=w1v.y; B1s[lr][lk+2]=w1v.z; B1s[lr][lk+3]=w1v.w;
        B3s[lr][lk+0]=w3v.x; B3s[lr][lk+1]=w3v.y; B3s[lr][lk+2]=w3v.z; B3s[lr][lk+3]=w3v.w;
        __syncthreads();
#pragma unroll
        for (int kk = 0; kk < 16; kk++) {
            float a[4], b1[4], b3[4];
#pragma unroll
            for (int i = 0; i < 4; i++) a[i]  = As [ty*4+i][kk];
#pragma unroll
            for (int j = 0; j < 4; j++) { b1[j] = B1s[tx*4+j][kk]; b3[j] = B3s[tx*4+j][kk]; }
#pragma unroll
            for (int i = 0; i < 4; i++)
#pragma unroll
                for (int j = 0; j < 4; j++) { a1[i][j] += a[i]*b1[j]; a3[i][j] += a[i]*b3[j]; }
        }
        __syncthreads();
    }
#pragma unroll
    for (int i = 0; i < 4; i++) {
        int r = rb + ty*4 + i;
        if (r < n) {
#pragma unroll
            for (int j = 0; j < 4; j++) {
                float g = a1[i][j], u = a3[i][j];
                float hv = g / (1.f + expf(-g)) * u;
                Hbuf[((size_t)e*NT + r)*Hh + cb + tx*4 + j] = hv;
            }
        }
    }
}

// ---------------- FFN down: out = Hbuf @ W2^T (scatter or residual) ---------
template<bool GROUPED>
__global__ void ffn_down_kernel(const float* __restrict__ Hbuf,
                                const float* __restrict__ W2,
                                float* __restrict__ Out,      // dense: g_h ; grouped: yslot
                                const int* __restrict__ tok,
                                const float* __restrict__ wt,
                                const int* __restrict__ cnt) {
    int e = GROUPED ? blockIdx.z : 0;
    int n = GROUPED ? cnt[e] : NT;
    int rb = blockIdx.y * 64;
    if (rb >= n) return;
    __shared__ float As[64][17], Bs[64][17];
    int t = threadIdx.x, tx = t & 15, ty = t >> 4;
    int cb = blockIdx.x * 64;
    int lr = t >> 2, lk = (t & 3) << 2;
    int ar = rb + lr; if (ar > n-1) ar = n-1;
    const float* arow = Hbuf + ((size_t)e*NT + ar)*Hh;
    const float* brow = W2 + (size_t)e*Dd*Hh + (size_t)(cb + lr)*Hh;
    float acc[4][4] = {};
    for (int k0 = 0; k0 < Hh; k0 += 16) {
        float4 av = *(const float4*)(arow + k0 + lk);
        float4 bv = *(const float4*)(brow + k0 + lk);
        As[lr][lk+0]=av.x; As[lr][lk+1]=av.y; As[lr][lk+2]=av.z; As[lr][lk+3]=av.w;
        Bs[lr][lk+0]=bv.x; Bs[lr][lk+1]=bv.y; Bs[lr][lk+2]=bv.z; Bs[lr][lk+3]=bv.w;
        __syncthreads();
#pragma unroll
        for (int kk = 0; kk < 16; kk++) {
            float a[4], b[4];
#pragma unroll
            for (int i = 0; i < 4; i++) a[i] = As[ty*4+i][kk];
#pragma unroll
            for (int j = 0; j < 4; j++) b[j] = Bs[tx*4+j][kk];
#pragma unroll
            for (int i = 0; i < 4; i++)
#pragma unroll
                for (int j = 0; j < 4; j++) acc[i][j] += a[i]*b[j];
        }
        __syncthreads();
    }
#pragma unroll
    for (int i = 0; i < 4; i++) {
        int r = rb + ty*4 + i;
        if (r < n) {
            if (GROUPED) {
                int pk = tok[e*NT + r];
                float w = wt[e*NT + r];
#pragma unroll
                for (int j = 0; j < 4; j++)
                    Out[(size_t)pk*Dd + cb + tx*4 + j] = w * acc[i][j];
            } else {
#pragma unroll
                for (int j = 0; j < 4; j++)
                    Out[(size_t)r*Dd + cb + tx*4 + j] += acc[i][j];
            }
        }
    }
}

// ---------------- combine: h += yslot[2t] + yslot[2t+1] ---------------------
__global__ void combine_kernel(float* __restrict__ h, const float* __restrict__ ys) {
    int idx = blockIdx.x*256 + threadIdx.x;
    if (idx >= NT*Dd) return;
    int tk = idx / Dd, d = idx - tk*Dd;
    h[idx] += ys[(size_t)(2*tk)*Dd + d] + ys[(size_t)(2*tk+1)*Dd + d];
}

// ---------------- host orchestration ----------------------------------------
extern "C" void kernel_launch(void* const* d_in, const int* in_sizes, int n_in,
                              void* d_out, int out_size) {
    (void)in_sizes; (void)n_in; (void)out_size;
    const float* x        = (const float*)d_in[0];
    const float* qkv_w    = (const float*)d_in[1];
    const float* out_w    = (const float*)d_in[2];
    const float* norm1_w  = (const float*)d_in[3];
    const float* norm2_w  = (const float*)d_in[4];
    const float* router_w = (const float*)d_in[5];
    const float* moe_w1   = (const float*)d_in[6];
    const float* moe_w2   = (const float*)d_in[7];
    const float* moe_w3   = (const float*)d_in[8];
    const float* f_w1     = (const float*)d_in[9];
    const float* f_w2     = (const float*)d_in[10];
    const float* f_w3     = (const float*)d_in[11];
    const float* norm_f   = (const float*)d_in[12];
    float* out = (float*)d_out;

    float *h, *xn, *qkv, *q, *k, *v, *attn, *hbuf, *yslot, *wt;
    int *cnt, *tok;
    cudaGetSymbolAddress((void**)&h,    g_h);
    cudaGetSymbolAddress((void**)&xn,   g_xn);
    cudaGetSymbolAddress((void**)&qkv,  g_qkv);
    cudaGetSymbolAddress((void**)&q,    g_q);
    cudaGetSymbolAddress((void**)&k,    g_k);
    cudaGetSymbolAddress((void**)&v,    g_v);
    cudaGetSymbolAddress((void**)&attn, g_attn);
    cudaGetSymbolAddress((void**)&hbuf, g_hbuf);
    cudaGetSymbolAddress((void**)&yslot,g_yslot);
    cudaGetSymbolAddress((void**)&cnt,  g_cnt);
    cudaGetSymbolAddress((void**)&tok,  g_tok);
    cudaGetSymbolAddress((void**)&wt,   g_wt);

    const int attn_smem = 3 * 64 * 65 * sizeof(float);   // 49,920 B
    cudaFuncSetAttribute(attn_kernel, cudaFuncAttributeMaxDynamicSharedMemorySize, attn_smem);

    cudaMemcpyAsync(h, x, (size_t)NT*Dd*sizeof(float), cudaMemcpyDeviceToDevice, 0);

    for (int l = 0; l < Ll; l++) {
        rmsnorm_kernel<<<NT, 256>>>(h, norm1_w + (size_t)l*Dd, xn);
        gemm_nt_kernel<<<dim3(1536/64, NT/64), 256>>>(
            xn, qkv_w + (size_t)l*1536*Dd, qkv, nullptr, 1536, Dd);
        split_rope_kernel<<<(NT*NHh*32 + 255)/256, 256>>>(qkv, q, k, v);
        attn_kernel<<<dim3(Tt/64, Bz*NHh), 256, attn_smem>>>(q, k, v, attn);
        gemm_nt_kernel<<<dim3(Dd/64, NT/64), 256>>>(
            attn, out_w + (size_t)l*Dd*Dd, h, h, Dd, Dd);
        rmsnorm_kernel<<<NT, 256>>>(h, norm2_w + (size_t)l*Dd, xn);

        if (l == 0 || l == 2) {                 // MoE layers
            int m = l / 2;
            cudaMemsetAsync(cnt, 0, Ee*sizeof(int), 0);
            router_kernel<<<(NT*32 + 127)/128, 128>>>(
                xn, router_w + (size_t)m*Ee*Dd, cnt, tok, wt);
            ffn_up_kernel<true><<<dim3(Hh/64, NT/64, Ee), 256>>>(
                xn, moe_w1 + (size_t)m*Ee*Hh*Dd, moe_w3 + (size_t)m*Ee*Hh*Dd,
                hbuf, tok, cnt);
            ffn_down_kernel<true><<<dim3(Dd/64, NT/64, Ee), 256>>>(
                hbuf, moe_w2 + (size_t)m*Ee*Dd*Hh, yslot, tok, wt, cnt);
            combine_kernel<<<(NT*Dd + 255)/256, 256>>>(h, yslot);
        } else {                                // dense SwiGLU layers
            int m = (l == 1) ? 0 : 1;
            ffn_up_kernel<false><<<dim3(Hh/64, NT/64, 1), 256>>>(
                xn, f_w1 + (size_t)m*Hh*Dd, f_w3 + (size_t)m*Hh*Dd,
                hbuf, nullptr, nullptr);
            ffn_down_kernel<false><<<dim3(Dd/64, NT/64, 1), 256>>>(
                hbuf, f_w2 + (size_t)m*Dd*Hh, h, nullptr, nullptr, nullptr);
        }
    }
    rmsnorm_kernel<<<NT, 256>>>(h, norm_f, out);
}

// round 6
// speedup vs baseline: 1.9163x; 1.9163x over previous
#include <cuda_runtime.h>
#include <math.h>
#include <stdint.h>

#define Bz 2
#define Tt 1024
#define Dd 512
#define NHh 8
#define Ll 4
#define Ee 8
#define Hh 2048
#define NT (Bz*Tt)

#define SZ_QKV ((size_t)Ll*1536*Dd)
#define SZ_OUT ((size_t)Ll*Dd*Dd)
#define SZ_MW  ((size_t)2*Ee*Hh*Dd)
#define SZ_FW  ((size_t)2*Hh*Dd)
#define OFF_QKV 0ull
#define OFF_OUT (OFF_QKV+SZ_QKV)
#define OFF_MW1 (OFF_OUT+SZ_OUT)
#define OFF_MW3 (OFF_MW1+SZ_MW)
#define OFF_MW2 (OFF_MW3+SZ_MW)
#define OFF_FW1 (OFF_MW2+SZ_MW)
#define OFF_FW3 (OFF_FW1+SZ_FW)
#define OFF_FW2 (OFF_FW3+SZ_FW)
#define WR_TOTAL (OFF_FW2+SZ_FW)

__device__ float g_h[NT*Dd];
__device__ float g_xn[NT*Dd];
__device__ float g_xn32[NT*Dd];
__device__ float g_qkv[NT*3*Dd];
__device__ float g_q[NT*Dd];
__device__ float g_k[NT*Dd];
__device__ float g_v[NT*Dd];
__device__ float g_attn[NT*Dd];
__device__ float g_hbuf[(size_t)Ee*NT*Hh];
__device__ float g_yslot[2*NT*Dd];
__device__ float g_wr[WR_TOTAL];
__device__ int   g_cnt[Ee];
__device__ int   g_tok[Ee*NT];
__device__ float g_wt[Ee*NT];

// ---------------- helpers -----------------------------------------------------
__device__ __forceinline__ uint32_t s2u(const void* p){
    uint32_t a;
    asm("{ .reg .u64 t; cvta.to.shared.u64 t, %1; cvt.u32.u64 %0, t; }":"=r"(a):"l"(p));
    return a;
}
__device__ __forceinline__ float to_tf32(float x){
    uint32_t u; asm("cvt.rn.tf32.f32 %0, %1;":"=r"(u):"f"(x));
    return __uint_as_float(u);
}
__device__ __forceinline__ void cp16(uint32_t dst, const void* src){
    asm volatile("cp.async.cg.shared.global [%0], [%1], 16;"::"r"(dst),"l"(src));
}
#define CP_COMMIT() asm volatile("cp.async.commit_group;")

#define MMA8(d,a,b0,b1) \
  asm volatile("mma.sync.aligned.m16n8k8.row.col.f32.tf32.tf32.f32 " \
    "{%0,%1,%2,%3},{%4,%5,%6,%7},{%8,%9},{%0,%1,%2,%3};" \
    : "+f"((d)[0]),"+f"((d)[1]),"+f"((d)[2]),"+f"((d)[3]) \
    : "r"((a)[0]),"r"((a)[1]),"r"((a)[2]),"r"((a)[3]),"r"(b0),"r"(b1))

// ============ tf32 mma.sync GEMM: C = A @ B^T ================================
// Tile: 128 rows x (FUSED?64:128) cols. 256 threads = 8 warps (4x2).
// FUSED: dual-output (B1,B3) swiglu epilogue. GROUPED: per-expert MoE.
// MODE 0 store, 1 +=, 2 weighted scatter.
template<bool FUSED, bool GROUPED, int MODE>
__global__ void __launch_bounds__(256) mm_kernel(
    const float* __restrict__ A, const float* __restrict__ B1, const float* __restrict__ B3,
    float* __restrict__ C, const int* __restrict__ cnt, const int* __restrict__ tok,
    const float* __restrict__ wtv, int K, int ldc, int nrows,
    long long sAe, long long sBe, long long sCe)
{
    constexpr int NJ = FUSED ? 4 : 8;
    __shared__ float As[2][128][20];
    __shared__ float Bs[2][128][20];
    int e = GROUPED ? blockIdx.z : 0;
    int n = GROUPED ? cnt[e] : nrows;
    int rb = blockIdx.y*128;
    if (rb >= n) return;
    int cb = blockIdx.x*(FUSED ? 64 : 128);
    if (GROUPED) {
        if (!FUSED) A += (size_t)e*sAe;
        B1 += (size_t)e*sBe;
        if (FUSED) B3 += (size_t)e*sBe;
        C += (size_t)e*sCe;
    }
    int t = threadIdx.x;
    int lane = t & 31, w = t >> 5;
    int wr = w >> 1, wc = w & 1;
    int tq = lane >> 2, tr = lane & 3;

    // per-thread gmem source pointers (2 rows each of A and B per chunk)
    const float* Ap[2]; const float* Bp[2];
#pragma unroll
    for (int i = 0; i < 2; i++) {
        int lin = t + i*256;
        int row = lin >> 2, kq = (lin & 3) << 2;
        int ar = rb + row; if (GROUPED && ar > n-1) ar = n-1;
        if (GROUPED && FUSED) Ap[i] = A + (size_t)(tok[(size_t)e*NT + ar] >> 1)*K + kq;
        else                  Ap[i] = A + (size_t)ar*K + kq;
        if (!FUSED) Bp[i] = B1 + (size_t)(cb + row)*K + kq;
        else {
            const float* bb = (row < 64) ? B1 : B3;
            Bp[i] = bb + (size_t)(cb + (row & 63))*K + kq;
        }
    }
    uint32_t sA = s2u(&As[0][0][0]), sB = s2u(&Bs[0][0][0]);

    float acc1[2][NJ][4];
    float acc3[2][NJ][4];
#pragma unroll
    for (int i = 0; i < 2; i++)
#pragma unroll
        for (int j = 0; j < NJ; j++)
#pragma unroll
            for (int q = 0; q < 4; q++) { acc1[i][j][q] = 0.f; acc3[i][j][q] = 0.f; }

    auto load = [&](int c, int s){
#pragma unroll
        for (int i = 0; i < 2; i++) {
            int lin = t + i*256;
            int row = lin >> 2, kq = (lin & 3) << 2;
            uint32_t off = (uint32_t)(((s*128 + row)*20 + kq)*4);
            cp16(sA + off, Ap[i] + (size_t)c*16);
            cp16(sB + off, Bp[i] + (size_t)c*16);
        }
        CP_COMMIT();
    };

    const int NC = K >> 4;
    load(0, 0);
    for (int c = 0; c < NC; c++) {
        int s = c & 1;
        if (c+1 < NC) { load(c+1, s^1); asm volatile("cp.async.wait_group 1;"); }
        else asm volatile("cp.async.wait_group 0;");
        __syncthreads();
#pragma unroll
        for (int ks = 0; ks < 2; ks++) {
            int k0 = ks*8;
            uint32_t a[2][4];
#pragma unroll
            for (int i = 0; i < 2; i++) {
                int r0 = wr*32 + i*16;
                a[i][0] = __float_as_uint(As[s][r0+tq  ][k0+tr  ]);
                a[i][1] = __float_as_uint(As[s][r0+tq+8][k0+tr  ]);
                a[i][2] = __float_as_uint(As[s][r0+tq  ][k0+tr+4]);
                a[i][3] = __float_as_uint(As[s][r0+tq+8][k0+tr+4]);
            }
#pragma unroll
            for (int j = 0; j < NJ; j++) {
                int bc = wc*(NJ*8) + j*8 + tq;
                uint32_t b0 = __float_as_uint(Bs[s][bc][k0+tr]);
                uint32_t b1 = __float_as_uint(Bs[s][bc][k0+tr+4]);
#pragma unroll
                for (int i = 0; i < 2; i++) MMA8(acc1[i][j], a[i], b0, b1);
                if (FUSED) {
                    uint32_t c0 = __float_as_uint(Bs[s][bc+64][k0+tr]);
                    uint32_t c1 = __float_as_uint(Bs[s][bc+64][k0+tr+4]);
#pragma unroll
                    for (int i = 0; i < 2; i++) MMA8(acc3[i][j], a[i], c0, c1);
                }
            }
        }
        __syncthreads();
    }

    // -------- epilogue --------
#pragma unroll
    for (int i = 0; i < 2; i++)
#pragma unroll
        for (int hh = 0; hh < 2; hh++) {
            int gr = rb + wr*32 + i*16 + tq + hh*8;
            if (GROUPED && gr >= n) continue;
            int orow = gr; float wv = 1.f;
            if (GROUPED && MODE == 2) {
                orow = tok[(size_t)e*NT + gr];
                wv   = wtv[(size_t)e*NT + gr];
            }
            float* cr = C + (size_t)orow*ldc;
#pragma unroll
            for (int j = 0; j < NJ; j++) {
                int gc = cb + wc*(NJ*8) + j*8 + tr*2;
                float v0 = acc1[i][j][hh*2], v1 = acc1[i][j][hh*2+1];
                if (FUSED) {
                    float u0 = acc3[i][j][hh*2], u1 = acc3[i][j][hh*2+1];
                    float2 o;
                    o.x = to_tf32(v0/(1.f+expf(-v0))*u0);
                    o.y = to_tf32(v1/(1.f+expf(-v1))*u1);
                    *(float2*)(cr + gc) = o;
                } else if (MODE == 0) {
                    float2 o = {v0, v1};
                    *(float2*)(cr + gc) = o;
                } else if (MODE == 1) {
                    float2 o = *(float2*)(cr + gc);
                    o.x += v0; o.y += v1;
                    *(float2*)(cr + gc) = o;
                } else {
                    float2 o = {wv*v0, wv*v1};
                    *(float2*)(cr + gc) = o;
                }
            }
        }
}

// ---------------- weight rounding fp32 -> RN tf32 ----------------------------
__global__ void round_copy(const float* __restrict__ s, float* __restrict__ d, int n4){
    int i = blockIdx.x*256 + threadIdx.x;
    if (i >= n4) return;
    float4 v = ((const float4*)s)[i];
    v.x=to_tf32(v.x); v.y=to_tf32(v.y); v.z=to_tf32(v.z); v.w=to_tf32(v.w);
    ((float4*)d)[i] = v;
}

// ---------------- rmsnorm (optionally rounded + raw copy) --------------------
template<bool ROUND>
__global__ void rmsnorm_kernel(const float* __restrict__ in, const float* __restrict__ w,
                               float* __restrict__ out, float* __restrict__ out32){
    int row = blockIdx.x;
    const float* x = in + (size_t)row*Dd;
    float s = 0.f;
    for (int j = threadIdx.x; j < Dd; j += 256) { float v = x[j]; s += v*v; }
    __shared__ float red[8];
    for (int o = 16; o; o >>= 1) s += __shfl_xor_sync(0xffffffffu, s, o);
    if ((threadIdx.x & 31) == 0) red[threadIdx.x>>5] = s;
    __syncthreads();
    if (threadIdx.x < 8) {
        float v = red[threadIdx.x];
        for (int o = 4; o; o >>= 1) v += __shfl_xor_sync(0xffu, v, o);
        if (threadIdx.x == 0) red[0] = v;
    }
    __syncthreads();
    float rms = rsqrtf(red[0]/(float)Dd + 1e-5f);
    for (int j = threadIdx.x; j < Dd; j += 256) {
        float v = w[j]*x[j]*rms;
        out[(size_t)row*Dd+j] = ROUND ? to_tf32(v) : v;
        if (out32) out32[(size_t)row*Dd+j] = v;
    }
}

// ---------------- qkv split + RoPE -------------------------------------------
__global__ void split_rope_kernel(const float* __restrict__ qkv, float* __restrict__ Q,
                                  float* __restrict__ K, float* __restrict__ V){
    int idx = blockIdx.x*256 + threadIdx.x;
    if (idx >= NT*NHh*32) return;
    int d = idx & 31, h = (idx>>5)&7, bt = idx>>8;
    int tt = bt & (Tt-1), b = bt>>10;
    float inv = expf(-(float)d*0.28782313662425575f);
    float sn, cs; sincosf((float)tt*inv, &sn, &cs);
    size_t bi = (size_t)bt*1536 + h*64 + d;
    float q1=qkv[bi], q2=qkv[bi+32], k1=qkv[bi+512], k2=qkv[bi+544], v1=qkv[bi+1024], v2=qkv[bi+1056];
    size_t oi = ((size_t)(b*NHh+h)*Tt + tt)*64 + d;
    Q[oi]=q1*cs-q2*sn; Q[oi+32]=q1*sn+q2*cs;
    K[oi]=k1*cs-k2*sn; K[oi+32]=k1*sn+k2*cs;
    V[oi]=v1; V[oi+32]=v2;
}

// ---------------- flash attention (causal, HD=64) ----------------------------
__global__ void attn_kernel(const float* __restrict__ Q, const float* __restrict__ K,
                            const float* __restrict__ V, float* __restrict__ Out){
    extern __shared__ float sm[];
    float* Qs = sm; float* KPs = sm + 64*65; float* Vs = sm + 2*64*65;
    int qt = blockIdx.x, bh = blockIdx.y, t = threadIdx.x;
    int rg = t>>4, cg = t&15;
    const float* Qb = Q + (size_t)bh*Tt*64;
    const float* Kb = K + (size_t)bh*Tt*64;
    const float* Vb = V + (size_t)bh*Tt*64;
#pragma unroll
    for (int i = 0; i < 4; i++) {
        int idx = t + i*256, r = idx>>4, c4 = (idx&15)<<2;
        float4 v4 = *(const float4*)(Qb + (size_t)(qt*64+r)*64 + c4);
        Qs[r*65+c4+0]=v4.x*0.125f; Qs[r*65+c4+1]=v4.y*0.125f;
        Qs[r*65+c4+2]=v4.z*0.125f; Qs[r*65+c4+3]=v4.w*0.125f;
    }
    float m[4]={-1e30f,-1e30f,-1e30f,-1e30f}, l[4]={0,0,0,0}, O[4][4]={};
    for (int kt = 0; kt <= qt; kt++) {
        __syncthreads();
#pragma unroll
        for (int i = 0; i < 4; i++) {
            int idx = t + i*256, r = idx>>4, c4 = (idx&15)<<2;
            float4 kv = *(const float4*)(Kb + (size_t)(kt*64+r)*64 + c4);
            KPs[r*65+c4+0]=kv.x; KPs[r*65+c4+1]=kv.y; KPs[r*65+c4+2]=kv.z; KPs[r*65+c4+3]=kv.w;
            float4 vv = *(const float4*)(Vb + (size_t)(kt*64+r)*64 + c4);
            Vs[r*65+c4+0]=vv.x; Vs[r*65+c4+1]=vv.y; Vs[r*65+c4+2]=vv.z; Vs[r*65+c4+3]=vv.w;
        }
        __syncthreads();
        float s[4][4] = {};
#pragma unroll
        for (int kk = 0; kk < 64; kk++) {
            float a[4], b[4];
#pragma unroll
            for (int i = 0; i < 4; i++) a[i] = Qs[(rg*4+i)*65+kk];
#pragma unroll
            for (int j = 0; j < 4; j++) b[j] = KPs[(cg*4+j)*65+kk];
#pragma unroll
            for (int i = 0; i < 4; i++)
#pragma unroll
                for (int j = 0; j < 4; j++) s[i][j] += a[i]*b[j];
        }
        if (kt == qt)
#pragma unroll
            for (int i = 0; i < 4; i++)
#pragma unroll
                for (int j = 0; j < 4; j++)
                    if (cg*4+j > rg*4+i) s[i][j] = -1e30f;
#pragma unroll
        for (int i = 0; i < 4; i++) {
            float rm = fmaxf(fmaxf(s[i][0],s[i][1]), fmaxf(s[i][2],s[i][3]));
            for (int o = 8; o; o >>= 1) rm = fmaxf(rm, __shfl_xor_sync(0xffffffffu, rm, o));
            float nm = fmaxf(m[i], rm), f = expf(m[i]-nm), rs = 0.f;
#pragma unroll
            for (int j = 0; j < 4; j++) { s[i][j] = expf(s[i][j]-nm); rs += s[i][j]; }
            for (int o = 8; o; o >>= 1) rs += __shfl_xor_sync(0xffffffffu, rs, o);
            l[i] = l[i]*f + rs; m[i] = nm;
#pragma unroll
            for (int j = 0; j < 4; j++) O[i][j] *= f;
        }
        __syncthreads();
#pragma unroll
        for (int i = 0; i < 4; i++)
#pragma unroll
            for (int j = 0; j < 4; j++) KPs[(rg*4+i)*65 + cg*4+j] = s[i][j];
        __syncthreads();
#pragma unroll
        for (int jk = 0; jk < 64; jk++) {
            float p[4], v[4];
#pragma unroll
            for (int i = 0; i < 4; i++) p[i] = KPs[(rg*4+i)*65+jk];
#pragma unroll
            for (int j = 0; j < 4; j++) v[j] = Vs[jk*65 + cg*4+j];
#pragma unroll
            for (int i = 0; i < 4; i++)
#pragma unroll
                for (int j = 0; j < 4; j++) O[i][j] += p[i]*v[j];
        }
    }
    int b = bh>>3, hh = bh&7;
#pragma unroll
    for (int i = 0; i < 4; i++) {
        float invl = 1.f/l[i];
        int qrow = qt*64 + rg*4 + i;
#pragma unroll
        for (int j = 0; j < 4; j++)
            Out[((size_t)(b*Tt+qrow))*Dd + hh*64 + cg*4 + j] = to_tf32(O[i][j]*invl);
    }
}

// ---------------- router (fp32, unrounded input) ------------------------------
__global__ void router_kernel(const float* __restrict__ X, const float* __restrict__ RW,
                              int* __restrict__ cnt, int* __restrict__ tok, float* __restrict__ wt){
    int g = blockIdx.x*blockDim.x + threadIdx.x;
    int warp = g>>5, lane = g&31;
    if (warp >= NT) return;
    const float* xr = X + (size_t)warp*Dd;
    float lg[Ee];
#pragma unroll
    for (int e = 0; e < Ee; e++) {
        const float* w = RW + (size_t)e*Dd;
        float s = 0.f;
        for (int j = lane; j < Dd; j += 32) s += xr[j]*w[j];
        for (int o = 16; o; o >>= 1) s += __shfl_xor_sync(0xffffffffu, s, o);
        lg[e] = s;
    }
    if (lane == 0) {
        int i0 = 0; float v0 = lg[0];
#pragma unroll
        for (int e = 1; e < Ee; e++) if (lg[e] > v0) { v0 = lg[e]; i0 = e; }
        int i1 = -1; float v1 = -3.4e38f;
#pragma unroll
        for (int e = 0; e < Ee; e++) if (e != i0 && lg[e] > v1) { v1 = lg[e]; i1 = e; }
        float e1 = expf(v1 - v0);
        float w0 = 1.f/(1.f+e1), w1 = e1/(1.f+e1);
        int p0 = atomicAdd(&cnt[i0], 1);
        tok[i0*NT+p0] = warp*2;   wt[i0*NT+p0] = w0;
        int p1 = atomicAdd(&cnt[i1], 1);
        tok[i1*NT+p1] = warp*2+1; wt[i1*NT+p1] = w1;
    }
}

__global__ void combine_kernel(float* __restrict__ h, const float* __restrict__ ys){
    int idx = blockIdx.x*256 + threadIdx.x;
    if (idx >= NT*Dd) return;
    int tk = idx/Dd, d = idx - tk*Dd;
    h[idx] += ys[(size_t)(2*tk)*Dd+d] + ys[(size_t)(2*tk+1)*Dd+d];
}

// ---------------- host orchestration ------------------------------------------
extern "C" void kernel_launch(void* const* d_in, const int* in_sizes, int n_in,
                              void* d_out, int out_size) {
    (void)in_sizes; (void)n_in; (void)out_size;
    const float* x        = (const float*)d_in[0];
    const float* qkv_w    = (const float*)d_in[1];
    const float* out_w    = (const float*)d_in[2];
    const float* norm1_w  = (const float*)d_in[3];
    const float* norm2_w  = (const float*)d_in[4];
    const float* router_w = (const float*)d_in[5];
    const float* moe_w1   = (const float*)d_in[6];
    const float* moe_w2   = (const float*)d_in[7];
    const float* moe_w3   = (const float*)d_in[8];
    const float* f_w1     = (const float*)d_in[9];
    const float* f_w2     = (const float*)d_in[10];
    const float* f_w3     = (const float*)d_in[11];
    const float* norm_f   = (const float*)d_in[12];
    float* out = (float*)d_out;

    float *h,*xn,*xn32,*qkv,*q,*k,*v,*attn,*hbuf,*yslot,*wt,*wr;
    int *cnt,*tok;
    cudaGetSymbolAddress((void**)&h, g_h);       cudaGetSymbolAddress((void**)&xn, g_xn);
    cudaGetSymbolAddress((void**)&xn32, g_xn32); cudaGetSymbolAddress((void**)&qkv, g_qkv);
    cudaGetSymbolAddress((void**)&q, g_q);       cudaGetSymbolAddress((void**)&k, g_k);
    cudaGetSymbolAddress((void**)&v, g_v);       cudaGetSymbolAddress((void**)&attn, g_attn);
    cudaGetSymbolAddress((void**)&hbuf, g_hbuf); cudaGetSymbolAddress((void**)&yslot, g_yslot);
    cudaGetSymbolAddress((void**)&wr, g_wr);     cudaGetSymbolAddress((void**)&cnt, g_cnt);
    cudaGetSymbolAddress((void**)&tok, g_tok);   cudaGetSymbolAddress((void**)&wt, g_wt);

    const int attn_smem = 3*64*65*sizeof(float);
    cudaFuncSetAttribute(attn_kernel, cudaFuncAttributeMaxDynamicSharedMemorySize, attn_smem);

    // one-time per-launch weight rounding to RN-tf32
    round_copy<<<(int)(SZ_QKV/4+255)/256,256>>>(qkv_w, wr+OFF_QKV, (int)(SZ_QKV/4));
    round_copy<<<(int)(SZ_OUT/4+255)/256,256>>>(out_w, wr+OFF_OUT, (int)(SZ_OUT/4));
    round_copy<<<(int)(SZ_MW/4+255)/256,256>>>(moe_w1, wr+OFF_MW1, (int)(SZ_MW/4));
    round_copy<<<(int)(SZ_MW/4+255)/256,256>>>(moe_w3, wr+OFF_MW3, (int)(SZ_MW/4));
    round_copy<<<(int)(SZ_MW/4+255)/256,256>>>(moe_w2, wr+OFF_MW2, (int)(SZ_MW/4));
    round_copy<<<(int)(SZ_FW/4+255)/256,256>>>(f_w1, wr+OFF_FW1, (int)(SZ_FW/4));
    round_copy<<<(int)(SZ_FW/4+255)/256,256>>>(f_w3, wr+OFF_FW3, (int)(SZ_FW/4));
    round_copy<<<(int)(SZ_FW/4+255)/256,256>>>(f_w2, wr+OFF_FW2, (int)(SZ_FW/4));

    cudaMemcpyAsync(h, x, (size_t)NT*Dd*sizeof(float), cudaMemcpyDeviceToDevice, 0);

    for (int l = 0; l < Ll; l++) {
        rmsnorm_kernel<true><<<NT,256>>>(h, norm1_w+(size_t)l*Dd, xn, nullptr);
        mm_kernel<false,false,0><<<dim3(12,16),256>>>(
            xn, wr+OFF_QKV+(size_t)l*1536*Dd, nullptr, qkv,
            nullptr,nullptr,nullptr, Dd, 1536, NT, 0,0,0);
        split_rope_kernel<<<(NT*NHh*32+255)/256,256>>>(qkv, q, k, v);
        attn_kernel<<<dim3(Tt/64, Bz*NHh),256,attn_smem>>>(q, k, v, attn);
        mm_kernel<false,false,1><<<dim3(4,16),256>>>(
            attn, wr+OFF_OUT+(size_t)l*Dd*Dd, nullptr, h,
            nullptr,nullptr,nullptr, Dd, Dd, NT, 0,0,0);

        if (l == 0 || l == 2) {
            int m = l/2;
            rmsnorm_kernel<true><<<NT,256>>>(h, norm2_w+(size_t)l*Dd, xn, xn32);
            cudaMemsetAsync(cnt, 0, Ee*sizeof(int), 0);
            router_kernel<<<(NT*32+127)/128,128>>>(xn32, router_w+(size_t)m*Ee*Dd, cnt, tok, wt);
            mm_kernel<true,true,0><<<dim3(Hh/64,16,Ee),256>>>(
                xn, wr+OFF_MW1+(size_t)m*Ee*Hh*Dd, wr+OFF_MW3+(size_t)m*Ee*Hh*Dd, hbuf,
                cnt, tok, nullptr, Dd, Hh, 0, 0, (long long)Hh*Dd, (long long)NT*Hh);
            mm_kernel<false,true,2><<<dim3(4,16,Ee),256>>>(
                hbuf, wr+OFF_MW2+(size_t)m*Ee*Dd*Hh, nullptr, yslot,
                cnt, tok, wt, Hh, Dd, 0, (long long)NT*Hh, (long long)Dd*Hh, 0);
            combine_kernel<<<(NT*Dd+255)/256,256>>>(h, yslot);
        } else {
            int m = (l == 1) ? 0 : 1;
            rmsnorm_kernel<true><<<NT,256>>>(h, norm2_w+(size_t)l*Dd, xn, nullptr);
            mm_kernel<true,false,0><<<dim3(Hh/64,16),256>>>(
                xn, wr+OFF_FW1+(size_t)m*Hh*Dd, wr+OFF_FW3+(size_t)m*Hh*Dd, hbuf,
                nullptr,nullptr,nullptr, Dd, Hh, NT, 0,0,0);
            mm_kernel<false,false,1><<<dim3(4,16),256>>>(
                hbuf, wr+OFF_FW2+(size_t)m*Dd*Hh, nullptr, h,
                nullptr,nullptr,nullptr, Hh, Dd, NT, 0,0,0);
        }
    }
    rmsnorm_kernel<false><<<NT,256>>>(h, norm_f, out, nullptr);
}

// round 7
// speedup vs baseline: 2.4142x; 1.2598x over previous
#include <cuda_runtime.h>
#include <math.h>
#include <stdint.h>

#define Bz 2
#define Tt 1024
#define Dd 512
#define NHh 8
#define Ll 4
#define Ee 8
#define Hh 2048
#define NT (Bz*Tt)

#define SZ_QKV ((size_t)Ll*1536*Dd)
#define SZ_OUT ((size_t)Ll*Dd*Dd)
#define SZ_MW  ((size_t)2*Ee*Hh*Dd)
#define SZ_FW  ((size_t)2*Hh*Dd)
#define OFF_QKV 0ull
#define OFF_OUT (OFF_QKV+SZ_QKV)
#define OFF_MW1 (OFF_OUT+SZ_OUT)
#define OFF_MW3 (OFF_MW1+SZ_MW)
#define OFF_MW2 (OFF_MW3+SZ_MW)
#define OFF_FW1 (OFF_MW2+SZ_MW)
#define OFF_FW3 (OFF_FW1+SZ_FW)
#define OFF_FW2 (OFF_FW3+SZ_FW)
#define WR_TOTAL (OFF_FW2+SZ_FW)

__device__ float g_h[NT*Dd];
__device__ float g_xn[NT*Dd];
__device__ float g_xn32[NT*Dd];
__device__ float g_qkv[NT*3*Dd];
__device__ float g_q[NT*Dd];
__device__ float g_k[NT*Dd];
__device__ float g_v[NT*Dd];
__device__ float g_attn[NT*Dd];
__device__ float g_hbuf[(size_t)Ee*NT*Hh];
__device__ float g_yslot[2*NT*Dd];
__device__ float g_wr[WR_TOTAL];
__device__ int   g_cnt[Ee];
__device__ int   g_tok[Ee*NT];
__device__ float g_wt[Ee*NT];

// ---------------- helpers -----------------------------------------------------
__device__ __forceinline__ uint32_t s2u(const void* p){
    uint32_t a;
    asm("{ .reg .u64 t; cvta.to.shared.u64 t, %1; cvt.u32.u64 %0, t; }":"=r"(a):"l"(p));
    return a;
}
__device__ __forceinline__ float to_tf32(float x){
    uint32_t u; asm("cvt.rn.tf32.f32 %0, %1;":"=r"(u):"f"(x));
    return __uint_as_float(u);
}
__device__ __forceinline__ void cp16(uint32_t dst, const void* src){
    asm volatile("cp.async.cg.shared.global [%0], [%1], 16;"::"r"(dst),"l"(src));
}
#define CP_COMMIT() asm volatile("cp.async.commit_group;")
#define fau __float_as_uint

#define MMA8(d,a,b0,b1) \
  asm volatile("mma.sync.aligned.m16n8k8.row.col.f32.tf32.tf32.f32 " \
    "{%0,%1,%2,%3},{%4,%5,%6,%7},{%8,%9},{%0,%1,%2,%3};" \
    : "+f"((d)[0]),"+f"((d)[1]),"+f"((d)[2]),"+f"((d)[3]) \
    : "r"((a)[0]),"r"((a)[1]),"r"((a)[2]),"r"((a)[3]),"r"(b0),"r"(b1))

// ============ tf32 mma.sync GEMM: C = A @ B^T ================================
template<bool FUSED, bool GROUPED, int MODE>
__global__ void __launch_bounds__(256) mm_kernel(
    const float* __restrict__ A, const float* __restrict__ B1, const float* __restrict__ B3,
    float* __restrict__ C, const int* __restrict__ cnt, const int* __restrict__ tok,
    const float* __restrict__ wtv, int K, int ldc, int nrows,
    long long sAe, long long sBe, long long sCe)
{
    constexpr int NJ = FUSED ? 4 : 8;
    __shared__ float As[2][128][20];
    __shared__ float Bs[2][128][20];
    int e = GROUPED ? blockIdx.z : 0;
    int n = GROUPED ? cnt[e] : nrows;
    int rb = blockIdx.y*128;
    if (rb >= n) return;
    int cb = blockIdx.x*(FUSED ? 64 : 128);
    if (GROUPED) {
        if (!FUSED) A += (size_t)e*sAe;
        B1 += (size_t)e*sBe;
        if (FUSED) B3 += (size_t)e*sBe;
        C += (size_t)e*sCe;
    }
    int t = threadIdx.x;
    int lane = t & 31, w = t >> 5;
    int wr = w >> 1, wc = w & 1;
    int tq = lane >> 2, tr = lane & 3;

    const float* Ap[2]; const float* Bp[2];
#pragma unroll
    for (int i = 0; i < 2; i++) {
        int lin = t + i*256;
        int row = lin >> 2, kq = (lin & 3) << 2;
        int ar = rb + row; if (GROUPED && ar > n-1) ar = n-1;
        if (GROUPED && FUSED) Ap[i] = A + (size_t)(tok[(size_t)e*NT + ar] >> 1)*K + kq;
        else                  Ap[i] = A + (size_t)ar*K + kq;
        if (!FUSED) Bp[i] = B1 + (size_t)(cb + row)*K + kq;
        else {
            const float* bb = (row < 64) ? B1 : B3;
            Bp[i] = bb + (size_t)(cb + (row & 63))*K + kq;
        }
    }
    uint32_t sA = s2u(&As[0][0][0]), sB = s2u(&Bs[0][0][0]);

    float acc1[2][NJ][4];
    float acc3[2][NJ][4];
#pragma unroll
    for (int i = 0; i < 2; i++)
#pragma unroll
        for (int j = 0; j < NJ; j++)
#pragma unroll
            for (int q = 0; q < 4; q++) { acc1[i][j][q] = 0.f; acc3[i][j][q] = 0.f; }

    auto load = [&](int c, int s){
#pragma unroll
        for (int i = 0; i < 2; i++) {
            int lin = t + i*256;
            int row = lin >> 2, kq = (lin & 3) << 2;
            uint32_t off = (uint32_t)(((s*128 + row)*20 + kq)*4);
            cp16(sA + off, Ap[i] + (size_t)c*16);
            cp16(sB + off, Bp[i] + (size_t)c*16);
        }
        CP_COMMIT();
    };

    const int NC = K >> 4;
    load(0, 0);
    for (int c = 0; c < NC; c++) {
        int s = c & 1;
        if (c+1 < NC) { load(c+1, s^1); asm volatile("cp.async.wait_group 1;"); }
        else asm volatile("cp.async.wait_group 0;");
        __syncthreads();
#pragma unroll
        for (int ks = 0; ks < 2; ks++) {
            int k0 = ks*8;
            uint32_t a[2][4];
#pragma unroll
            for (int i = 0; i < 2; i++) {
                int r0 = wr*32 + i*16;
                a[i][0] = fau(As[s][r0+tq  ][k0+tr  ]);
                a[i][1] = fau(As[s][r0+tq+8][k0+tr  ]);
                a[i][2] = fau(As[s][r0+tq  ][k0+tr+4]);
                a[i][3] = fau(As[s][r0+tq+8][k0+tr+4]);
            }
#pragma unroll
            for (int j = 0; j < NJ; j++) {
                int bc = wc*(NJ*8) + j*8 + tq;
                uint32_t b0 = fau(Bs[s][bc][k0+tr]);
                uint32_t b1 = fau(Bs[s][bc][k0+tr+4]);
#pragma unroll
                for (int i = 0; i < 2; i++) MMA8(acc1[i][j], a[i], b0, b1);
                if (FUSED) {
                    uint32_t c0 = fau(Bs[s][bc+64][k0+tr]);
                    uint32_t c1 = fau(Bs[s][bc+64][k0+tr+4]);
#pragma unroll
                    for (int i = 0; i < 2; i++) MMA8(acc3[i][j], a[i], c0, c1);
                }
            }
        }
        __syncthreads();
    }

#pragma unroll
    for (int i = 0; i < 2; i++)
#pragma unroll
        for (int hh = 0; hh < 2; hh++) {
            int gr = rb + wr*32 + i*16 + tq + hh*8;
            if (GROUPED && gr >= n) continue;
            int orow = gr; float wv = 1.f;
            if (GROUPED && MODE == 2) {
                orow = tok[(size_t)e*NT + gr];
                wv   = wtv[(size_t)e*NT + gr];
            }
            float* cr = C + (size_t)orow*ldc;
#pragma unroll
            for (int j = 0; j < NJ; j++) {
                int gc = cb + wc*(NJ*8) + j*8 + tr*2;
                float v0 = acc1[i][j][hh*2], v1 = acc1[i][j][hh*2+1];
                if (FUSED) {
                    float u0 = acc3[i][j][hh*2], u1 = acc3[i][j][hh*2+1];
                    float2 o;
                    o.x = to_tf32(v0/(1.f+__expf(-v0))*u0);
                    o.y = to_tf32(v1/(1.f+__expf(-v1))*u1);
                    *(float2*)(cr + gc) = o;
                } else if (MODE == 0) {
                    float2 o = {v0, v1};
                    *(float2*)(cr + gc) = o;
                } else if (MODE == 1) {
                    float2 o = *(float2*)(cr + gc);
                    o.x += v0; o.y += v1;
                    *(float2*)(cr + gc) = o;
                } else {
                    float2 o = {wv*v0, wv*v1};
                    *(float2*)(cr + gc) = o;
                }
            }
        }
}

// ---------------- weight rounding fp32 -> RN tf32 ----------------------------
__global__ void round_copy(const float* __restrict__ s, float* __restrict__ d, int n4){
    int i = blockIdx.x*256 + threadIdx.x;
    if (i >= n4) return;
    float4 v = ((const float4*)s)[i];
    v.x=to_tf32(v.x); v.y=to_tf32(v.y); v.z=to_tf32(v.z); v.w=to_tf32(v.w);
    ((float4*)d)[i] = v;
}

// ---------------- rmsnorm ------------------------------------------------------
template<bool ROUND>
__global__ void rmsnorm_kernel(const float* __restrict__ in, const float* __restrict__ w,
                               float* __restrict__ out, float* __restrict__ out32){
    int row = blockIdx.x;
    const float* x = in + (size_t)row*Dd;
    float s = 0.f;
    for (int j = threadIdx.x; j < Dd; j += 256) { float v = x[j]; s += v*v; }
    __shared__ float red[8];
    for (int o = 16; o; o >>= 1) s += __shfl_xor_sync(0xffffffffu, s, o);
    if ((threadIdx.x & 31) == 0) red[threadIdx.x>>5] = s;
    __syncthreads();
    if (threadIdx.x < 8) {
        float v = red[threadIdx.x];
        for (int o = 4; o; o >>= 1) v += __shfl_xor_sync(0xffu, v, o);
        if (threadIdx.x == 0) red[0] = v;
    }
    __syncthreads();
    float rms = rsqrtf(red[0]/(float)Dd + 1e-5f);
    for (int j = threadIdx.x; j < Dd; j += 256) {
        float v = w[j]*x[j]*rms;
        out[(size_t)row*Dd+j] = ROUND ? to_tf32(v) : v;
        if (out32) out32[(size_t)row*Dd+j] = v;
    }
}

// ---------------- qkv split + RoPE (RN-tf32 outputs, Q pre-scaled) ------------
__global__ void split_rope_kernel(const float* __restrict__ qkv, float* __restrict__ Q,
                                  float* __restrict__ K, float* __restrict__ V){
    int idx = blockIdx.x*256 + threadIdx.x;
    if (idx >= NT*NHh*32) return;
    int d = idx & 31, h = (idx>>5)&7, bt = idx>>8;
    int tt = bt & (Tt-1), b = bt>>10;
    float inv = expf(-(float)d*0.28782313662425575f);
    float sn, cs; sincosf((float)tt*inv, &sn, &cs);
    size_t bi = (size_t)bt*1536 + h*64 + d;
    float q1=qkv[bi], q2=qkv[bi+32], k1=qkv[bi+512], k2=qkv[bi+544], v1=qkv[bi+1024], v2=qkv[bi+1056];
    size_t oi = ((size_t)(b*NHh+h)*Tt + tt)*64 + d;
    Q[oi]   =to_tf32((q1*cs-q2*sn)*0.125f); Q[oi+32]=to_tf32((q1*sn+q2*cs)*0.125f);
    K[oi]   =to_tf32(k1*cs-k2*sn);          K[oi+32]=to_tf32(k1*sn+k2*cs);
    V[oi]   =to_tf32(v1);                   V[oi+32]=to_tf32(v2);
}

// ---------------- tensor-core flash attention (causal, HD=64) -----------------
// grid (8, BH=16), block 128 (4 warps). CTA x handles q-tiles x and 15-x
// (uniform 17 k-tiles). smem: K/V double-buffered 64x72 + P 64x72.
#define LDP 72
__global__ void __launch_bounds__(128) attn_tc_kernel(
    const float* __restrict__ Q, const float* __restrict__ K,
    const float* __restrict__ V, float* __restrict__ Out)
{
    extern __shared__ float sm[];
    float* Ks = sm;                  // [2][64][LDP]
    float* Vs = sm + 2*64*LDP;       // [2][64][LDP]
    float* Ps = sm + 4*64*LDP;       // [64][LDP]
    int bh = blockIdx.y;
    int t = threadIdx.x, lane = t & 31, w = t >> 5;
    int tq = lane >> 2, tr = lane & 3;
    const float* Qb = Q + (size_t)bh*Tt*64;
    const float* Kb = K + (size_t)bh*Tt*64;
    const float* Vb = V + (size_t)bh*Tt*64;
    int b = bh >> 3, hh = bh & 7;
    uint32_t sK = s2u(Ks), sV = s2u(Vs);

    auto load_kv = [&](int kt, int buf){
        const float* ks = Kb + (size_t)kt*64*64;
        const float* vs = Vb + (size_t)kt*64*64;
        uint32_t kd = sK + buf*64*LDP*4;
        uint32_t vd = sV + buf*64*LDP*4;
#pragma unroll
        for (int i = 0; i < 8; i++) {
            int u = t + i*128;
            int row = u >> 4, seg = u & 15;
            uint32_t off = (uint32_t)((row*LDP + seg*4)*4);
            cp16(kd + off, ks + row*64 + seg*4);
            cp16(vd + off, vs + row*64 + seg*4);
        }
        CP_COMMIT();
    };

    for (int pass = 0; pass < 2; pass++) {
        int qt = pass ? (15 - (int)blockIdx.x) : (int)blockIdx.x;
        int nkt = qt + 1;
        __syncthreads();                 // all warps done with prior smem use
        load_kv(0, 0);
        // stage Q tile into Ps
        for (int u = t; u < 64*16; u += 128) {
            int row = u >> 4, seg = u & 15;
            *(float4*)&Ps[row*LDP + seg*4] = *(const float4*)(Qb + (size_t)(qt*64+row)*64 + seg*4);
        }
        __syncthreads();
        uint32_t qa[8][4];
        int r0 = w*16 + tq;
#pragma unroll
        for (int ks = 0; ks < 8; ks++) {
            qa[ks][0] = fau(Ps[ r0   *LDP + ks*8+tr  ]);
            qa[ks][1] = fau(Ps[(r0+8)*LDP + ks*8+tr  ]);
            qa[ks][2] = fau(Ps[ r0   *LDP + ks*8+tr+4]);
            qa[ks][3] = fau(Ps[(r0+8)*LDP + ks*8+tr+4]);
        }
        float o[8][4];
#pragma unroll
        for (int j = 0; j < 8; j++)
#pragma unroll
            for (int q = 0; q < 4; q++) o[j][q] = 0.f;
        float m0 = -1e30f, m1 = -1e30f, l0 = 0.f, l1 = 0.f;

        for (int kt = 0; kt < nkt; kt++) {
            int buf = kt & 1;
            __syncthreads();             // prior users of next buffer done
            if (kt+1 < nkt) { load_kv(kt+1, buf^1); asm volatile("cp.async.wait_group 1;"); }
            else asm volatile("cp.async.wait_group 0;");
            __syncthreads();

            const float* Kt = Ks + buf*64*LDP;
            const float* Vt = Vs + buf*64*LDP;
            float s[8][4];
#pragma unroll
            for (int j = 0; j < 8; j++)
#pragma unroll
                for (int q = 0; q < 4; q++) s[j][q] = 0.f;
#pragma unroll
            for (int nf = 0; nf < 8; nf++) {
#pragma unroll
                for (int ks = 0; ks < 8; ks++) {
                    uint32_t b0 = fau(Kt[(nf*8+tq)*LDP + ks*8+tr  ]);
                    uint32_t b1 = fau(Kt[(nf*8+tq)*LDP + ks*8+tr+4]);
                    MMA8(s[nf], qa[ks], b0, b1);
                }
            }
            if (kt == qt) {
                int qr0 = qt*64 + r0, qr1 = qr0 + 8;
#pragma unroll
                for (int nf = 0; nf < 8; nf++) {
                    int kc = kt*64 + nf*8 + 2*tr;
                    if (kc   > qr0) s[nf][0] = -1e30f;
                    if (kc+1 > qr0) s[nf][1] = -1e30f;
                    if (kc   > qr1) s[nf][2] = -1e30f;
                    if (kc+1 > qr1) s[nf][3] = -1e30f;
                }
            }
            // online softmax (rows r0, r0+8; quad lanes share a row)
            float rm0 = -1e30f, rm1 = -1e30f;
#pragma unroll
            for (int nf = 0; nf < 8; nf++) {
                rm0 = fmaxf(rm0, fmaxf(s[nf][0], s[nf][1]));
                rm1 = fmaxf(rm1, fmaxf(s[nf][2], s[nf][3]));
            }
            rm0 = fmaxf(rm0, __shfl_xor_sync(0xffffffffu, rm0, 1));
            rm0 = fmaxf(rm0, __shfl_xor_sync(0xffffffffu, rm0, 2));
            rm1 = fmaxf(rm1, __shfl_xor_sync(0xffffffffu, rm1, 1));
            rm1 = fmaxf(rm1, __shfl_xor_sync(0xffffffffu, rm1, 2));
            float nm0 = fmaxf(m0, rm0), nm1 = fmaxf(m1, rm1);
            float f0 = __expf(m0 - nm0), f1 = __expf(m1 - nm1);
            float rs0 = 0.f, rs1 = 0.f;
#pragma unroll
            for (int nf = 0; nf < 8; nf++) {
                float p0 = __expf(s[nf][0] - nm0);
                float p1 = __expf(s[nf][1] - nm0);
                float p2 = __expf(s[nf][2] - nm1);
                float p3 = __expf(s[nf][3] - nm1);
                rs0 += p0 + p1; rs1 += p2 + p3;
                Ps[ r0   *LDP + nf*8 + 2*tr    ] = to_tf32(p0);
                Ps[ r0   *LDP + nf*8 + 2*tr + 1] = to_tf32(p1);
                Ps[(r0+8)*LDP + nf*8 + 2*tr    ] = to_tf32(p2);
                Ps[(r0+8)*LDP + nf*8 + 2*tr + 1] = to_tf32(p3);
            }
            rs0 += __shfl_xor_sync(0xffffffffu, rs0, 1);
            rs0 += __shfl_xor_sync(0xffffffffu, rs0, 2);
            rs1 += __shfl_xor_sync(0xffffffffu, rs1, 1);
            rs1 += __shfl_xor_sync(0xffffffffu, rs1, 2);
            l0 = l0*f0 + rs0; m0 = nm0;
            l1 = l1*f1 + rs1; m1 = nm1;
#pragma unroll
            for (int j = 0; j < 8; j++) { o[j][0]*=f0; o[j][1]*=f0; o[j][2]*=f1; o[j][3]*=f1; }
            __syncwarp();                // P rows are warp-private
            uint32_t pa[8][4];
#pragma unroll
            for (int ks = 0; ks < 8; ks++) {
                pa[ks][0] = fau(Ps[ r0   *LDP + ks*8+tr  ]);
                pa[ks][1] = fau(Ps[(r0+8)*LDP + ks*8+tr  ]);
                pa[ks][2] = fau(Ps[ r0   *LDP + ks*8+tr+4]);
                pa[ks][3] = fau(Ps[(r0+8)*LDP + ks*8+tr+4]);
            }
#pragma unroll
            for (int nf = 0; nf < 8; nf++) {
#pragma unroll
                for (int ks = 0; ks < 8; ks++) {
                    uint32_t b0 = fau(Vt[(ks*8+tr  )*LDP + nf*8+tq]);
                    uint32_t b1 = fau(Vt[(ks*8+tr+4)*LDP + nf*8+tq]);
                    MMA8(o[nf], pa[ks], b0, b1);
                }
            }
        }
        // write output
        float il0 = 1.f/l0, il1 = 1.f/l1;
        int qr = qt*64 + r0;
        float* o0 = Out + ((size_t)(b*Tt + qr    ))*Dd + hh*64;
        float* o1 = Out + ((size_t)(b*Tt + qr + 8))*Dd + hh*64;
#pragma unroll
        for (int nf = 0; nf < 8; nf++) {
            int gc = nf*8 + 2*tr;
            float2 a = { to_tf32(o[nf][0]*il0), to_tf32(o[nf][1]*il0) };
            float2 c = { to_tf32(o[nf][2]*il1), to_tf32(o[nf][3]*il1) };
            *(float2*)(o0 + gc) = a;
            *(float2*)(o1 + gc) = c;
        }
    }
}

// ---------------- router (fp32, unrounded input) ------------------------------
__global__ void router_kernel(const float* __restrict__ X, const float* __restrict__ RW,
                              int* __restrict__ cnt, int* __restrict__ tok, float* __restrict__ wt){
    int g = blockIdx.x*blockDim.x + threadIdx.x;
    int warp = g>>5, lane = g&31;
    if (warp >= NT) return;
    const float* xr = X + (size_t)warp*Dd;
    float lg[Ee];
#pragma unroll
    for (int e = 0; e < Ee; e++) {
        const float* w = RW + (size_t)e*Dd;
        float s = 0.f;
        for (int j = lane; j < Dd; j += 32) s += xr[j]*w[j];
        for (int o = 16; o; o >>= 1) s += __shfl_xor_sync(0xffffffffu, s, o);
        lg[e] = s;
    }
    if (lane == 0) {
        int i0 = 0; float v0 = lg[0];
#pragma unroll
        for (int e = 1; e < Ee; e++) if (lg[e] > v0) { v0 = lg[e]; i0 = e; }
        int i1 = -1; float v1 = -3.4e38f;
#pragma unroll
        for (int e = 0; e < Ee; e++) if (e != i0 && lg[e] > v1) { v1 = lg[e]; i1 = e; }
        float e1 = expf(v1 - v0);
        float w0 = 1.f/(1.f+e1), w1 = e1/(1.f+e1);
        int p0 = atomicAdd(&cnt[i0], 1);
        tok[i0*NT+p0] = warp*2;   wt[i0*NT+p0] = w0;
        int p1 = atomicAdd(&cnt[i1], 1);
        tok[i1*NT+p1] = warp*2+1; wt[i1*NT+p1] = w1;
    }
}

__global__ void combine_kernel(float* __restrict__ h, const float* __restrict__ ys){
    int idx = blockIdx.x*256 + threadIdx.x;
    if (idx >= NT*Dd) return;
    int tk = idx/Dd, d = idx - tk*Dd;
    h[idx] += ys[(size_t)(2*tk)*Dd+d] + ys[(size_t)(2*tk+1)*Dd+d];
}

// ---------------- host orchestration ------------------------------------------
extern "C" void kernel_launch(void* const* d_in, const int* in_sizes, int n_in,
                              void* d_out, int out_size) {
    (void)in_sizes; (void)n_in; (void)out_size;
    const float* x        = (const float*)d_in[0];
    const float* qkv_w    = (const float*)d_in[1];
    const float* out_w    = (const float*)d_in[2];
    const float* norm1_w  = (const float*)d_in[3];
    const float* norm2_w  = (const float*)d_in[4];
    const float* router_w = (const float*)d_in[5];
    const float* moe_w1   = (const float*)d_in[6];
    const float* moe_w2   = (const float*)d_in[7];
    const float* moe_w3   = (const float*)d_in[8];
    const float* f_w1     = (const float*)d_in[9];
    const float* f_w2     = (const float*)d_in[10];
    const float* f_w3     = (const float*)d_in[11];
    const float* norm_f   = (const float*)d_in[12];
    float* out = (float*)d_out;

    float *h,*xn,*xn32,*qkv,*q,*k,*v,*attn,*hbuf,*yslot,*wt,*wr;
    int *cnt,*tok;
    cudaGetSymbolAddress((void**)&h, g_h);       cudaGetSymbolAddress((void**)&xn, g_xn);
    cudaGetSymbolAddress((void**)&xn32, g_xn32); cudaGetSymbolAddress((void**)&qkv, g_qkv);
    cudaGetSymbolAddress((void**)&q, g_q);       cudaGetSymbolAddress((void**)&k, g_k);
    cudaGetSymbolAddress((void**)&v, g_v);       cudaGetSymbolAddress((void**)&attn, g_attn);
    cudaGetSymbolAddress((void**)&hbuf, g_hbuf); cudaGetSymbolAddress((void**)&yslot, g_yslot);
    cudaGetSymbolAddress((void**)&wr, g_wr);     cudaGetSymbolAddress((void**)&cnt, g_cnt);
    cudaGetSymbolAddress((void**)&tok, g_tok);   cudaGetSymbolAddress((void**)&wt, g_wt);

    const int attn_smem = 5*64*LDP*sizeof(float);   // 92,160 B
    cudaFuncSetAttribute(attn_tc_kernel, cudaFuncAttributeMaxDynamicSharedMemorySize, attn_smem);

    // per-launch weight rounding to RN-tf32
    round_copy<<<(int)(SZ_QKV/4+255)/256,256>>>(qkv_w, wr+OFF_QKV, (int)(SZ_QKV/4));
    round_copy<<<(int)(SZ_OUT/4+255)/256,256>>>(out_w, wr+OFF_OUT, (int)(SZ_OUT/4));
    round_copy<<<(int)(SZ_MW/4+255)/256,256>>>(moe_w1, wr+OFF_MW1, (int)(SZ_MW/4));
    round_copy<<<(int)(SZ_MW/4+255)/256,256>>>(moe_w3, wr+OFF_MW3, (int)(SZ_MW/4));
    round_copy<<<(int)(SZ_MW/4+255)/256,256>>>(moe_w2, wr+OFF_MW2, (int)(SZ_MW/4));
    round_copy<<<(int)(SZ_FW/4+255)/256,256>>>(f_w1, wr+OFF_FW1, (int)(SZ_FW/4));
    round_copy<<<(int)(SZ_FW/4+255)/256,256>>>(f_w3, wr+OFF_FW3, (int)(SZ_FW/4));
    round_copy<<<(int)(SZ_FW/4+255)/256,256>>>(f_w2, wr+OFF_FW2, (int)(SZ_FW/4));

    cudaMemcpyAsync(h, x, (size_t)NT*Dd*sizeof(float), cudaMemcpyDeviceToDevice, 0);

    for (int l = 0; l < Ll; l++) {
        rmsnorm_kernel<true><<<NT,256>>>(h, norm1_w+(size_t)l*Dd, xn, nullptr);
        mm_kernel<false,false,0><<<dim3(12,16),256>>>(
            xn, wr+OFF_QKV+(size_t)l*1536*Dd, nullptr, qkv,
            nullptr,nullptr,nullptr, Dd, 1536, NT, 0,0,0);
        split_rope_kernel<<<(NT*NHh*32+255)/256,256>>>(qkv, q, k, v);
        attn_tc_kernel<<<dim3(8, Bz*NHh),128,attn_smem>>>(q, k, v, attn);
        mm_kernel<false,false,1><<<dim3(4,16),256>>>(
            attn, wr+OFF_OUT+(size_t)l*Dd*Dd, nullptr, h,
            nullptr,nullptr,nullptr, Dd, Dd, NT, 0,0,0);

        if (l == 0 || l == 2) {
            int m = l/2;
            rmsnorm_kernel<true><<<NT,256>>>(h, norm2_w+(size_t)l*Dd, xn, xn32);
            cudaMemsetAsync(cnt, 0, Ee*sizeof(int), 0);
            router_kernel<<<(NT*32+127)/128,128>>>(xn32, router_w+(size_t)m*Ee*Dd, cnt, tok, wt);
            mm_kernel<true,true,0><<<dim3(Hh/64,16,Ee),256>>>(
                xn, wr+OFF_MW1+(size_t)m*Ee*Hh*Dd, wr+OFF_MW3+(size_t)m*Ee*Hh*Dd, hbuf,
                cnt, tok, nullptr, Dd, Hh, 0, 0, (long long)Hh*Dd, (long long)NT*Hh);
            mm_kernel<false,true,2><<<dim3(4,16,Ee),256>>>(
                hbuf, wr+OFF_MW2+(size_t)m*Ee*Dd*Hh, nullptr, yslot,
                cnt, tok, wt, Hh, Dd, 0, (long long)NT*Hh, (long long)Dd*Hh, 0);
            combine_kernel<<<(NT*Dd+255)/256,256>>>(h, yslot);
        } else {
            int m = (l == 1) ? 0 : 1;
            rmsnorm_kernel<true><<<NT,256>>>(h, norm2_w+(size_t)l*Dd, xn, nullptr);
            mm_kernel<true,false,0><<<dim3(Hh/64,16),256>>>(
                xn, wr+OFF_FW1+(size_t)m*Hh*Dd, wr+OFF_FW3+(size_t)m*Hh*Dd, hbuf,
                nullptr,nullptr,nullptr, Dd, Hh, NT, 0,0,0);
            mm_kernel<false,false,1><<<dim3(4,16),256>>>(
                hbuf, wr+OFF_FW2+(size_t)m*Dd*Hh, nullptr, h,
                nullptr,nullptr,nullptr, Hh, Dd, NT, 0,0,0);
        }
    }
    rmsnorm_kernel<false><<<NT,256>>>(h, norm_f, out, nullptr);
}

// round 9
// speedup vs baseline: 2.9733x; 1.2316x over previous
#include <cuda_runtime.h>
#include <math.h>
#include <stdint.h>

#define Bz 2
#define Tt 1024
#define Dd 512
#define NHh 8
#define Ll 4
#define Ee 8
#define Hh 2048
#define NT (Bz*Tt)

#define SZ_QKV ((size_t)Ll*1536*Dd)
#define SZ_OUT ((size_t)Ll*Dd*Dd)
#define SZ_MW  ((size_t)2*Ee*Hh*Dd)
#define SZ_FW  ((size_t)2*Hh*Dd)
#define OFF_QKV 0ull
#define OFF_OUT (OFF_QKV+SZ_QKV)
#define OFF_MW1 (OFF_OUT+SZ_OUT)
#define OFF_MW3 (OFF_MW1+SZ_MW)
#define OFF_MW2 (OFF_MW3+SZ_MW)
#define OFF_FW1 (OFF_MW2+SZ_MW)
#define OFF_FW3 (OFF_FW1+SZ_FW)
#define OFF_FW2 (OFF_FW3+SZ_FW)
#define WR_TOTAL (OFF_FW2+SZ_FW)

__device__ float g_h[NT*Dd];
__device__ float g_xn[NT*Dd];
__device__ float g_xn32[NT*Dd];
__device__ float g_qkv[NT*3*Dd];
__device__ float g_q[NT*Dd];
__device__ float g_k[NT*Dd];
__device__ float g_v[NT*Dd];
__device__ float g_attn[NT*Dd];
__device__ float g_hbuf[(size_t)Ee*NT*Hh];
__device__ float g_yslot[2*NT*Dd];
__device__ float g_wr[WR_TOTAL];
__device__ int   g_cnt[Ee];
__device__ int   g_tok[Ee*NT];
__device__ float g_wt[Ee*NT];

// ---------------- helpers -----------------------------------------------------
__device__ __forceinline__ uint32_t s2u(const void* p){
    uint32_t a;
    asm("{ .reg .u64 t; cvta.to.shared.u64 t, %1; cvt.u32.u64 %0, t; }":"=r"(a):"l"(p));
    return a;
}
__device__ __forceinline__ float to_tf32(float x){
    uint32_t u; asm("cvt.rn.tf32.f32 %0, %1;":"=r"(u):"f"(x));
    return __uint_as_float(u);
}
__device__ __forceinline__ void cp16(uint32_t dst, const void* src){
    asm volatile("cp.async.cg.shared.global [%0], [%1], 16;"::"r"(dst),"l"(src));
}
#define CP_COMMIT() asm volatile("cp.async.commit_group;")
#define fau __float_as_uint

#define MMA8(d,a,b0,b1) \
  asm volatile("mma.sync.aligned.m16n8k8.row.col.f32.tf32.tf32.f32 " \
    "{%0,%1,%2,%3},{%4,%5,%6,%7},{%8,%9},{%0,%1,%2,%3};" \
    : "+f"((d)[0]),"+f"((d)[1]),"+f"((d)[2]),"+f"((d)[3]) \
    : "r"((a)[0]),"r"((a)[1]),"r"((a)[2]),"r"((a)[3]),"r"(b0),"r"(b1))

// ============ tf32 mma.sync GEMM: C = A @ B^T ================================
// Tile: WROWS rows x (FUSED?64:128) cols. 256 threads = 8 warps.
// Warp grid: (WROWS/32) rows x (8/(WROWS/32)) cols. K-chunk = 32, stride 36.
template<int WROWS, bool FUSED, bool GROUPED, int MODE>
__global__ void __launch_bounds__(256) mm_kernel(
    const float* __restrict__ A, const float* __restrict__ B1, const float* __restrict__ B3,
    float* __restrict__ C, const int* __restrict__ cnt, const int* __restrict__ tok,
    const float* __restrict__ wtv, int K, int ldc, int nrows,
    long long sAe, long long sBe, long long sCe)
{
    constexpr int WRN   = WROWS/32;            // warp rows (2 or 4)
    constexpr int WCN   = 8/WRN;               // warp cols (4 or 2)
    constexpr int NCOLS = FUSED ? 64 : 128;    // OUTPUT tile width
    constexpr int NJ    = NCOLS/(WCN*8);       // n-frags per warp
    constexpr int LDS   = 36;
    constexpr int AV    = WROWS/32;            // A cp16 per thread per chunk
    extern __shared__ float sm[];
    float* As = sm;                            // [2][WROWS][36]
    float* Bs = sm + 2*WROWS*LDS;              // [2][128][36]

    int e = GROUPED ? blockIdx.z : 0;
    int n = GROUPED ? cnt[e] : nrows;
    int rb = blockIdx.y*WROWS;
    if (rb >= n) return;
    int cb = blockIdx.x*NCOLS;
    if (GROUPED) {
        if (!FUSED) A += (size_t)e*sAe;
        B1 += (size_t)e*sBe;
        if (FUSED) B3 += (size_t)e*sBe;
        C += (size_t)e*sCe;
    }
    int t = threadIdx.x;
    int lane = t & 31, w = t >> 5;
    int wr = w / WCN, wc = w % WCN;
    int tq = lane >> 2, tr = lane & 3;

    const float* Ap[AV]; const float* Bp[4];
#pragma unroll
    for (int i = 0; i < AV; i++) {
        int lin = t + i*256;
        int row = lin >> 3, kq = (lin & 7) << 2;
        int ar = rb + row; if (GROUPED && ar > n-1) ar = n-1;
        if (GROUPED && FUSED) Ap[i] = A + (size_t)(tok[(size_t)e*NT + ar] >> 1)*K + kq;
        else                  Ap[i] = A + (size_t)ar*K + kq;
    }
#pragma unroll
    for (int i = 0; i < 4; i++) {
        int lin = t + i*256;
        int row = lin >> 3, kq = (lin & 7) << 2;
        if (!FUSED) Bp[i] = B1 + (size_t)(cb + row)*K + kq;
        else {
            const float* bb = (row < 64) ? B1 : B3;
            Bp[i] = bb + (size_t)(cb + (row & 63))*K + kq;
        }
    }
    uint32_t sA = s2u(As), sB = s2u(Bs);

    float acc1[2][NJ][4];
    float acc3[FUSED?2:1][NJ][4];
#pragma unroll
    for (int i = 0; i < 2; i++)
#pragma unroll
        for (int j = 0; j < NJ; j++)
#pragma unroll
            for (int q = 0; q < 4; q++) { acc1[i][j][q] = 0.f; if (FUSED) acc3[i][j][q] = 0.f; }

    auto load = [&](int c, int s){
#pragma unroll
        for (int i = 0; i < AV; i++) {
            int lin = t + i*256;
            int row = lin >> 3, kq = (lin & 7) << 2;
            cp16(sA + (uint32_t)(((s*WROWS + row)*LDS + kq)*4), Ap[i] + (size_t)c*32);
        }
#pragma unroll
        for (int i = 0; i < 4; i++) {
            int lin = t + i*256;
            int row = lin >> 3, kq = (lin & 7) << 2;
            cp16(sB + (uint32_t)(((s*128 + row)*LDS + kq)*4), Bp[i] + (size_t)c*32);
        }
        CP_COMMIT();
    };

    const int NC = K >> 5;
    load(0, 0);
    for (int c = 0; c < NC; c++) {
        int s = c & 1;
        if (c+1 < NC) { load(c+1, s^1); asm volatile("cp.async.wait_group 1;"); }
        else asm volatile("cp.async.wait_group 0;");
        __syncthreads();
        const float* Ab = As + (size_t)s*WROWS*LDS;
        const float* Bb = Bs + (size_t)s*128*LDS;
#pragma unroll
        for (int ks = 0; ks < 4; ks++) {
            int k0 = ks*8;
            uint32_t a[2][4];
#pragma unroll
            for (int i = 0; i < 2; i++) {
                int r0 = wr*32 + i*16;
                a[i][0] = fau(Ab[(r0+tq  )*LDS + k0+tr  ]);
                a[i][1] = fau(Ab[(r0+tq+8)*LDS + k0+tr  ]);
                a[i][2] = fau(Ab[(r0+tq  )*LDS + k0+tr+4]);
                a[i][3] = fau(Ab[(r0+tq+8)*LDS + k0+tr+4]);
            }
#pragma unroll
            for (int j = 0; j < NJ; j++) {
                int bc = wc*(NJ*8) + j*8 + tq;
                uint32_t b0 = fau(Bb[bc*LDS + k0+tr]);
                uint32_t b1 = fau(Bb[bc*LDS + k0+tr+4]);
#pragma unroll
                for (int i = 0; i < 2; i++) MMA8(acc1[i][j], a[i], b0, b1);
                if (FUSED) {
                    uint32_t c0 = fau(Bb[(bc+64)*LDS + k0+tr]);
                    uint32_t c1 = fau(Bb[(bc+64)*LDS + k0+tr+4]);
#pragma unroll
                    for (int i = 0; i < 2; i++) MMA8(acc3[i][j], a[i], c0, c1);
                }
            }
        }
        __syncthreads();
    }

    // -------- epilogue --------
#pragma unroll
    for (int i = 0; i < 2; i++)
#pragma unroll
        for (int hh = 0; hh < 2; hh++) {
            int gr = rb + wr*32 + i*16 + tq + hh*8;
            if (GROUPED && gr >= n) continue;
            int orow = gr; float wv = 1.f;
            if (GROUPED && MODE == 2) {
                orow = tok[(size_t)e*NT + gr];
                wv   = wtv[(size_t)e*NT + gr];
            }
            float* cr = C + (size_t)orow*ldc;
#pragma unroll
            for (int j = 0; j < NJ; j++) {
                int gc = cb + wc*(NJ*8) + j*8 + tr*2;
                float v0 = acc1[i][j][hh*2], v1 = acc1[i][j][hh*2+1];
                if (FUSED) {
                    float u0 = acc3[i][j][hh*2], u1 = acc3[i][j][hh*2+1];
                    float2 o;
                    o.x = to_tf32(v0/(1.f+__expf(-v0))*u0);
                    o.y = to_tf32(v1/(1.f+__expf(-v1))*u1);
                    *(float2*)(cr + gc) = o;
                } else if (MODE == 0) {
                    float2 o = {v0, v1};
                    *(float2*)(cr + gc) = o;
                } else if (MODE == 1) {
                    float2 o = *(float2*)(cr + gc);
                    o.x += v0; o.y += v1;
                    *(float2*)(cr + gc) = o;
                } else {
                    float2 o = {wv*v0, wv*v1};
                    *(float2*)(cr + gc) = o;
                }
            }
        }
}

// ---------------- weight rounding fp32 -> RN tf32 ----------------------------
__global__ void round_copy(const float* __restrict__ s, float* __restrict__ d, int n4){
    int i = blockIdx.x*256 + threadIdx.x;
    if (i >= n4) return;
    float4 v = ((const float4*)s)[i];
    v.x=to_tf32(v.x); v.y=to_tf32(v.y); v.z=to_tf32(v.z); v.w=to_tf32(v.w);
    ((float4*)d)[i] = v;
}

// ---------------- rmsnorm ------------------------------------------------------
template<bool ROUND>
__global__ void rmsnorm_kernel(const float* __restrict__ in, const float* __restrict__ w,
                               float* __restrict__ out, float* __restrict__ out32){
    int row = blockIdx.x;
    const float* x = in + (size_t)row*Dd;
    float s = 0.f;
    for (int j = threadIdx.x; j < Dd; j += 256) { float v = x[j]; s += v*v; }
    __shared__ float red[8];
    for (int o = 16; o; o >>= 1) s += __shfl_xor_sync(0xffffffffu, s, o);
    if ((threadIdx.x & 31) == 0) red[threadIdx.x>>5] = s;
    __syncthreads();
    if (threadIdx.x < 8) {
        float v = red[threadIdx.x];
        for (int o = 4; o; o >>= 1) v += __shfl_xor_sync(0xffu, v, o);
        if (threadIdx.x == 0) red[0] = v;
    }
    __syncthreads();
    float rms = rsqrtf(red[0]/(float)Dd + 1e-5f);
    for (int j = threadIdx.x; j < Dd; j += 256) {
        float v = w[j]*x[j]*rms;
        out[(size_t)row*Dd+j] = ROUND ? to_tf32(v) : v;
        if (out32) out32[(size_t)row*Dd+j] = v;
    }
}

// ---------------- qkv split + RoPE (RN-tf32 outputs, Q pre-scaled) ------------
__global__ void split_rope_kernel(const float* __restrict__ qkv, float* __restrict__ Q,
                                  float* __restrict__ K, float* __restrict__ V){
    int idx = blockIdx.x*256 + threadIdx.x;
    if (idx >= NT*NHh*32) return;
    int d = idx & 31, h = (idx>>5)&7, bt = idx>>8;
    int tt = bt & (Tt-1), b = bt>>10;
    float inv = expf(-(float)d*0.28782313662425575f);
    float sn, cs; sincosf((float)tt*inv, &sn, &cs);
    size_t bi = (size_t)bt*1536 + h*64 + d;
    float q1=qkv[bi], q2=qkv[bi+32], k1=qkv[bi+512], k2=qkv[bi+544], v1=qkv[bi+1024], v2=qkv[bi+1056];
    size_t oi = ((size_t)(b*NHh+h)*Tt + tt)*64 + d;
    Q[oi]   =to_tf32((q1*cs-q2*sn)*0.125f); Q[oi+32]=to_tf32((q1*sn+q2*cs)*0.125f);
    K[oi]   =to_tf32(k1*cs-k2*sn);          K[oi+32]=to_tf32(k1*sn+k2*cs);
    V[oi]   =to_tf32(v1);                   V[oi+32]=to_tf32(v2);
}

// ---------------- tensor-core flash attention (causal, HD=64) -----------------
#define LDP 72
__global__ void __launch_bounds__(128) attn_tc_kernel(
    const float* __restrict__ Q, const float* __restrict__ K,
    const float* __restrict__ V, float* __restrict__ Out)
{
    extern __shared__ float sm[];
    float* Ks = sm;                  // [2][64][LDP]
    float* Vs = sm + 2*64*LDP;       // [2][64][LDP]
    float* Ps = sm + 4*64*LDP;       // [64][LDP]
    int bh = blockIdx.y;
    int t = threadIdx.x, lane = t & 31, w = t >> 5;
    int tq = lane >> 2, tr = lane & 3;
    const float* Qb = Q + (size_t)bh*Tt*64;
    const float* Kb = K + (size_t)bh*Tt*64;
    const float* Vb = V + (size_t)bh*Tt*64;
    int b = bh >> 3, hh = bh & 7;
    uint32_t sK = s2u(Ks), sV = s2u(Vs);

    auto load_kv = [&](int kt, int buf){
        const float* ks = Kb + (size_t)kt*64*64;
        const float* vs = Vb + (size_t)kt*64*64;
        uint32_t kd = sK + buf*64*LDP*4;
        uint32_t vd = sV + buf*64*LDP*4;
#pragma unroll
        for (int i = 0; i < 8; i++) {
            int u = t + i*128;
            int row = u >> 4, seg = u & 15;
            uint32_t off = (uint32_t)((row*LDP + seg*4)*4);
            cp16(kd + off, ks + row*64 + seg*4);
            cp16(vd + off, vs + row*64 + seg*4);
        }
        CP_COMMIT();
    };

    for (int pass = 0; pass < 2; pass++) {
        int qt = pass ? (15 - (int)blockIdx.x) : (int)blockIdx.x;
        int nkt = qt + 1;
        __syncthreads();
        load_kv(0, 0);
        for (int u = t; u < 64*16; u += 128) {
            int row = u >> 4, seg = u & 15;
            *(float4*)&Ps[row*LDP + seg*4] = *(const float4*)(Qb + (size_t)(qt*64+row)*64 + seg*4);
        }
        __syncthreads();
        uint32_t qa[8][4];
        int r0 = w*16 + tq;
#pragma unroll
        for (int ks = 0; ks < 8; ks++) {
            qa[ks][0] = fau(Ps[ r0   *LDP + ks*8+tr  ]);
            qa[ks][1] = fau(Ps[(r0+8)*LDP + ks*8+tr  ]);
            qa[ks][2] = fau(Ps[ r0   *LDP + ks*8+tr+4]);
            qa[ks][3] = fau(Ps[(r0+8)*LDP + ks*8+tr+4]);
        }
        float o[8][4];
#pragma unroll
        for (int j = 0; j < 8; j++)
#pragma unroll
            for (int q = 0; q < 4; q++) o[j][q] = 0.f;
        float m0 = -1e30f, m1 = -1e30f, l0 = 0.f, l1 = 0.f;

        for (int kt = 0; kt < nkt; kt++) {
            int buf = kt & 1;
            __syncthreads();
            if (kt+1 < nkt) { load_kv(kt+1, buf^1); asm volatile("cp.async.wait_group 1;"); }
            else asm volatile("cp.async.wait_group 0;");
            __syncthreads();

            const float* Kt = Ks + buf*64*LDP;
            const float* Vt = Vs + buf*64*LDP;
            float s[8][4];
#pragma unroll
            for (int j = 0; j < 8; j++)
#pragma unroll
                for (int q = 0; q < 4; q++) s[j][q] = 0.f;
#pragma unroll
            for (int nf = 0; nf < 8; nf++) {
#pragma unroll
                for (int ks = 0; ks < 8; ks++) {
                    uint32_t b0 = fau(Kt[(nf*8+tq)*LDP + ks*8+tr  ]);
                    uint32_t b1 = fau(Kt[(nf*8+tq)*LDP + ks*8+tr+4]);
                    MMA8(s[nf], qa[ks], b0, b1);
                }
            }
            if (kt == qt) {
                int qr0 = qt*64 + r0, qr1 = qr0 + 8;
#pragma unroll
                for (int nf = 0; nf < 8; nf++) {
                    int kc = kt*64 + nf*8 + 2*tr;
                    if (kc   > qr0) s[nf][0] = -1e30f;
                    if (kc+1 > qr0) s[nf][1] = -1e30f;
                    if (kc   > qr1) s[nf][2] = -1e30f;
                    if (kc+1 > qr1) s[nf][3] = -1e30f;
                }
            }
            float rm0 = -1e30f, rm1 = -1e30f;
#pragma unroll
            for (int nf = 0; nf < 8; nf++) {
                rm0 = fmaxf(rm0, fmaxf(s[nf][0], s[nf][1]));
                rm1 = fmaxf(rm1, fmaxf(s[nf][2], s[nf][3]));
            }
            rm0 = fmaxf(rm0, __shfl_xor_sync(0xffffffffu, rm0, 1));
            rm0 = fmaxf(rm0, __shfl_xor_sync(0xffffffffu, rm0, 2));
            rm1 = fmaxf(rm1, __shfl_xor_sync(0xffffffffu, rm1, 1));
            rm1 = fmaxf(rm1, __shfl_xor_sync(0xffffffffu, rm1, 2));
            float nm0 = fmaxf(m0, rm0), nm1 = fmaxf(m1, rm1);
            float f0 = __expf(m0 - nm0), f1 = __expf(m1 - nm1);
            float rs0 = 0.f, rs1 = 0.f;
#pragma unroll
            for (int nf = 0; nf < 8; nf++) {
                float p0 = __expf(s[nf][0] - nm0);
                float p1 = __expf(s[nf][1] - nm0);
                float p2 = __expf(s[nf][2] - nm1);
                float p3 = __expf(s[nf][3] - nm1);
                rs0 += p0 + p1; rs1 += p2 + p3;
                Ps[ r0   *LDP + nf*8 + 2*tr    ] = to_tf32(p0);
                Ps[ r0   *LDP + nf*8 + 2*tr + 1] = to_tf32(p1);
                Ps[(r0+8)*LDP + nf*8 + 2*tr    ] = to_tf32(p2);
                Ps[(r0+8)*LDP + nf*8 + 2*tr + 1] = to_tf32(p3);
            }
            rs0 += __shfl_xor_sync(0xffffffffu, rs0, 1);
            rs0 += __shfl_xor_sync(0xffffffffu, rs0, 2);
            rs1 += __shfl_xor_sync(0xffffffffu, rs1, 1);
            rs1 += __shfl_xor_sync(0xffffffffu, rs1, 2);
            l0 = l0*f0 + rs0; m0 = nm0;
            l1 = l1*f1 + rs1; m1 = nm1;
#pragma unroll
            for (int j = 0; j < 8; j++) { o[j][0]*=f0; o[j][1]*=f0; o[j][2]*=f1; o[j][3]*=f1; }
            __syncwarp();
            uint32_t pa[8][4];
#pragma unroll
            for (int ks = 0; ks < 8; ks++) {
                pa[ks][0] = fau(Ps[ r0   *LDP + ks*8+tr  ]);
                pa[ks][1] = fau(Ps[(r0+8)*LDP + ks*8+tr  ]);
                pa[ks][2] = fau(Ps[ r0   *LDP + ks*8+tr+4]);
                pa[ks][3] = fau(Ps[(r0+8)*LDP + ks*8+tr+4]);
            }
#pragma unroll
            for (int nf = 0; nf < 8; nf++) {
#pragma unroll
                for (int ks = 0; ks < 8; ks++) {
                    uint32_t b0 = fau(Vt[(ks*8+tr  )*LDP + nf*8+tq]);
                    uint32_t b1 = fau(Vt[(ks*8+tr+4)*LDP + nf*8+tq]);
                    MMA8(o[nf], pa[ks], b0, b1);
                }
            }
        }
        float il0 = 1.f/l0, il1 = 1.f/l1;
        int qr = qt*64 + r0;
        float* o0 = Out + ((size_t)(b*Tt + qr    ))*Dd + hh*64;
        float* o1 = Out + ((size_t)(b*Tt + qr + 8))*Dd + hh*64;
#pragma unroll
        for (int nf = 0; nf < 8; nf++) {
            int gc = nf*8 + 2*tr;
            float2 a = { to_tf32(o[nf][0]*il0), to_tf32(o[nf][1]*il0) };
            float2 c = { to_tf32(o[nf][2]*il1), to_tf32(o[nf][3]*il1) };
            *(float2*)(o0 + gc) = a;
            *(float2*)(o1 + gc) = c;
        }
    }
}

// ---------------- router (fp32, unrounded input) ------------------------------
__global__ void router_kernel(const float* __restrict__ X, const float* __restrict__ RW,
                              int* __restrict__ cnt, int* __restrict__ tok, float* __restrict__ wt){
    int g = blockIdx.x*blockDim.x + threadIdx.x;
    int warp = g>>5, lane = g&31;
    if (warp >= NT) return;
    const float* xr = X + (size_t)warp*Dd;
    float lg[Ee];
#pragma unroll
    for (int e = 0; e < Ee; e++) {
        const float* w = RW + (size_t)e*Dd;
        float s = 0.f;
        for (int j = lane; j < Dd; j += 32) s += xr[j]*w[j];
        for (int o = 16; o; o >>= 1) s += __shfl_xor_sync(0xffffffffu, s, o);
        lg[e] = s;
    }
    if (lane == 0) {
        int i0 = 0; float v0 = lg[0];
#pragma unroll
        for (int e = 1; e < Ee; e++) if (lg[e] > v0) { v0 = lg[e]; i0 = e; }
        int i1 = -1; float v1 = -3.4e38f;
#pragma unroll
        for (int e = 0; e < Ee; e++) if (e != i0 && lg[e] > v1) { v1 = lg[e]; i1 = e; }
        float e1 = expf(v1 - v0);
        float w0 = 1.f/(1.f+e1), w1 = e1/(1.f+e1);
        int p0 = atomicAdd(&cnt[i0], 1);
        tok[i0*NT+p0] = warp*2;   wt[i0*NT+p0] = w0;
        int p1 = atomicAdd(&cnt[i1], 1);
        tok[i1*NT+p1] = warp*2+1; wt[i1*NT+p1] = w1;
    }
}

__global__ void combine_kernel(float* __restrict__ h, const float* __restrict__ ys){
    int idx = blockIdx.x*256 + threadIdx.x;
    if (idx >= NT*Dd) return;
    int tk = idx/Dd, d = idx - tk*Dd;
    h[idx] += ys[(size_t)(2*tk)*Dd+d] + ys[(size_t)(2*tk+1)*Dd+d];
}

// ---------------- host orchestration ------------------------------------------
extern "C" void kernel_launch(void* const* d_in, const int* in_sizes, int n_in,
                              void* d_out, int out_size) {
    (void)in_sizes; (void)n_in; (void)out_size;
    const float* x        = (const float*)d_in[0];
    const float* qkv_w    = (const float*)d_in[1];
    const float* out_w    = (const float*)d_in[2];
    const float* norm1_w  = (const float*)d_in[3];
    const float* norm2_w  = (const float*)d_in[4];
    const float* router_w = (const float*)d_in[5];
    const float* moe_w1   = (const float*)d_in[6];
    const float* moe_w2   = (const float*)d_in[7];
    const float* moe_w3   = (const float*)d_in[8];
    const float* f_w1     = (const float*)d_in[9];
    const float* f_w2     = (const float*)d_in[10];
    const float* f_w3     = (const float*)d_in[11];
    const float* norm_f   = (const float*)d_in[12];
    float* out = (float*)d_out;

    float *h,*xn,*xn32,*qkv,*q,*k,*v,*attn,*hbuf,*yslot,*wt,*wr;
    int *cnt,*tok;
    cudaGetSymbolAddress((void**)&h, g_h);       cudaGetSymbolAddress((void**)&xn, g_xn);
    cudaGetSymbolAddress((void**)&xn32, g_xn32); cudaGetSymbolAddress((void**)&qkv, g_qkv);
    cudaGetSymbolAddress((void**)&q, g_q);       cudaGetSymbolAddress((void**)&k, g_k);
    cudaGetSymbolAddress((void**)&v, g_v);       cudaGetSymbolAddress((void**)&attn, g_attn);
    cudaGetSymbolAddress((void**)&hbuf, g_hbuf); cudaGetSymbolAddress((void**)&yslot, g_yslot);
    cudaGetSymbolAddress((void**)&wr, g_wr);     cudaGetSymbolAddress((void**)&cnt, g_cnt);
    cudaGetSymbolAddress((void**)&tok, g_tok);   cudaGetSymbolAddress((void**)&wt, g_wt);

    const int attn_smem = 5*64*LDP*sizeof(float);              // 92,160 B
    cudaFuncSetAttribute(attn_tc_kernel, cudaFuncAttributeMaxDynamicSharedMemorySize, attn_smem);
    const int SM64  = (2*64*36 + 2*128*36)*4;                  // 55,296 B
    const int SM128 = (2*128*36 + 2*128*36)*4;                 // 73,728 B
    cudaFuncSetAttribute(mm_kernel<64 ,false,false,0>, cudaFuncAttributeMaxDynamicSharedMemorySize, SM64);
    cudaFuncSetAttribute(mm_kernel<64 ,false,false,1>, cudaFuncAttributeMaxDynamicSharedMemorySize, SM64);
    cudaFuncSetAttribute(mm_kernel<64 ,false,true ,2>, cudaFuncAttributeMaxDynamicSharedMemorySize, SM64);
    cudaFuncSetAttribute(mm_kernel<128,true ,false,0>, cudaFuncAttributeMaxDynamicSharedMemorySize, SM128);
    cudaFuncSetAttribute(mm_kernel<128,true ,true ,0>, cudaFuncAttributeMaxDynamicSharedMemorySize, SM128);

    // per-launch weight rounding to RN-tf32
    round_copy<<<(int)(SZ_QKV/4+255)/256,256>>>(qkv_w, wr+OFF_QKV, (int)(SZ_QKV/4));
    round_copy<<<(int)(SZ_OUT/4+255)/256,256>>>(out_w, wr+OFF_OUT, (int)(SZ_OUT/4));
    round_copy<<<(int)(SZ_MW/4+255)/256,256>>>(moe_w1, wr+OFF_MW1, (int)(SZ_MW/4));
    round_copy<<<(int)(SZ_MW/4+255)/256,256>>>(moe_w3, wr+OFF_MW3, (int)(SZ_MW/4));
    round_copy<<<(int)(SZ_MW/4+255)/256,256>>>(moe_w2, wr+OFF_MW2, (int)(SZ_MW/4));
    round_copy<<<(int)(SZ_FW/4+255)/256,256>>>(f_w1, wr+OFF_FW1, (int)(SZ_FW/4));
    round_copy<<<(int)(SZ_FW/4+255)/256,256>>>(f_w3, wr+OFF_FW3, (int)(SZ_FW/4));
    round_copy<<<(int)(SZ_FW/4+255)/256,256>>>(f_w2, wr+OFF_FW2, (int)(SZ_FW/4));

    cudaMemcpyAsync(h, x, (size_t)NT*Dd*sizeof(float), cudaMemcpyDeviceToDevice, 0);

    for (int l = 0; l < Ll; l++) {
        rmsnorm_kernel<true><<<NT,256>>>(h, norm1_w+(size_t)l*Dd, xn, nullptr);
        mm_kernel<64,false,false,0><<<dim3(12,32),256,SM64>>>(
            xn, wr+OFF_QKV+(size_t)l*1536*Dd, nullptr, qkv,
            nullptr,nullptr,nullptr, Dd, 1536, NT, 0,0,0);
        split_rope_kernel<<<(NT*NHh*32+255)/256,256>>>(qkv, q, k, v);
        attn_tc_kernel<<<dim3(8, Bz*NHh),128,attn_smem>>>(q, k, v, attn);
        mm_kernel<64,false,false,1><<<dim3(4,32),256,SM64>>>(
            attn, wr+OFF_OUT+(size_t)l*Dd*Dd, nullptr, h,
            nullptr,nullptr,nullptr, Dd, Dd, NT, 0,0,0);

        if (l == 0 || l == 2) {
            int m = l/2;
            rmsnorm_kernel<true><<<NT,256>>>(h, norm2_w+(size_t)l*Dd, xn, xn32);
            cudaMemsetAsync(cnt, 0, Ee*sizeof(int), 0);
            router_kernel<<<(NT*32+127)/128,128>>>(xn32, router_w+(size_t)m*Ee*Dd, cnt, tok, wt);
            mm_kernel<128,true,true,0><<<dim3(Hh/64,16,Ee),256,SM128>>>(
                xn, wr+OFF_MW1+(size_t)m*Ee*Hh*Dd, wr+OFF_MW3+(size_t)m*Ee*Hh*Dd, hbuf,
                cnt, tok, nullptr, Dd, Hh, 0, 0, (long long)Hh*Dd, (long long)NT*Hh);
            mm_kernel<64,false,true,2><<<dim3(4,32,Ee),256,SM64>>>(
                hbuf, wr+OFF_MW2+(size_t)m*Ee*Dd*Hh, nullptr, yslot,
                cnt, tok, wt, Hh, Dd, 0, (long long)NT*Hh, (long long)Dd*Hh, 0);
            combine_kernel<<<(NT*Dd+255)/256,256>>>(h, yslot);
        } else {
            int m = (l == 1) ? 0 : 1;
            rmsnorm_kernel<true><<<NT,256>>>(h, norm2_w+(size_t)l*Dd, xn, nullptr);
            mm_kernel<128,true,false,0><<<dim3(Hh/64,16),256,SM128>>>(
                xn, wr+OFF_FW1+(size_t)m*Hh*Dd, wr+OFF_FW3+(size_t)m*Hh*Dd, hbuf,
                nullptr,nullptr,nullptr, Dd, Hh, NT, 0,0,0);
            mm_kernel<64,false,false,1><<<dim3(4,32),256,SM64>>>(
                hbuf, wr+OFF_FW2+(size_t)m*Dd*Hh, nullptr, h,
                nullptr,nullptr,nullptr, Hh, Dd, NT, 0,0,0);
        }
    }
    rmsnorm_kernel<false><<<NT,256>>>(h, norm_f, out, nullptr);
}

// round 10
// speedup vs baseline: 2.9930x; 1.0066x over previous
#include <cuda_runtime.h>
#include <math.h>
#include <stdint.h>

#define Bz 2
#define Tt 1024
#define Dd 512
#define NHh 8
#define Ll 4
#define Ee 8
#define Hh 2048
#define NT (Bz*Tt)

#define SZ_QKV ((size_t)Ll*1536*Dd)
#define SZ_OUT ((size_t)Ll*Dd*Dd)
#define SZ_MW  ((size_t)2*Ee*Hh*Dd)
#define SZ_MW1 (SZ_MW/2)               /* one m-index worth */
#define SZ_FW  ((size_t)2*Hh*Dd)
#define OFF_QKV 0ull
#define OFF_OUT (OFF_QKV+SZ_QKV)
#define OFF_MW1 (OFF_OUT+SZ_OUT)
#define OFF_MW3 (OFF_MW1+SZ_MW)
#define OFF_MW2 (OFF_MW3+SZ_MW)
#define OFF_FW1 (OFF_MW2+SZ_MW)
#define OFF_FW3 (OFF_FW1+SZ_FW)
#define OFF_FW2 (OFF_FW3+SZ_FW)
#define WR_TOTAL (OFF_FW2+SZ_FW)

__device__ float g_h[NT*Dd];
__device__ float g_xn[NT*Dd];
__device__ float g_xn32[NT*Dd];
__device__ float g_qkv[NT*3*Dd];
__device__ float g_q[NT*Dd];
__device__ float g_k[NT*Dd];
__device__ float g_v[NT*Dd];
__device__ float g_attn[NT*Dd];
__device__ float g_hbuf[(size_t)Ee*NT*Hh];
__device__ float g_wr[WR_TOTAL];
__device__ int   g_cnt[Ee];
__device__ int   g_tok[Ee*NT];
__device__ float g_wt[Ee*NT];

// ---------------- helpers -----------------------------------------------------
__device__ __forceinline__ uint32_t s2u(const void* p){
    uint32_t a;
    asm("{ .reg .u64 t; cvta.to.shared.u64 t, %1; cvt.u32.u64 %0, t; }":"=r"(a):"l"(p));
    return a;
}
__device__ __forceinline__ float to_tf32(float x){
    uint32_t u; asm("cvt.rn.tf32.f32 %0, %1;":"=r"(u):"f"(x));
    return __uint_as_float(u);
}
__device__ __forceinline__ void cp16(uint32_t dst, const void* src){
    asm volatile("cp.async.cg.shared.global [%0], [%1], 16;"::"r"(dst),"l"(src));
}
#define CP_COMMIT() asm volatile("cp.async.commit_group;")
#define fau __float_as_uint

#define MMA8(d,a,b0,b1) \
  asm volatile("mma.sync.aligned.m16n8k8.row.col.f32.tf32.tf32.f32 " \
    "{%0,%1,%2,%3},{%4,%5,%6,%7},{%8,%9},{%0,%1,%2,%3};" \
    : "+f"((d)[0]),"+f"((d)[1]),"+f"((d)[2]),"+f"((d)[3]) \
    : "r"((a)[0]),"r"((a)[1]),"r"((a)[2]),"r"((a)[3]),"r"(b0),"r"(b1))

// ============ tf32 mma.sync GEMM: C = A @ B^T ================================
// Tile: WROWS rows x (FUSED?64:128) cols. 256 threads = 8 warps.
// MODE 0 store, 1 +=, 3 weighted atomic scatter-add into token rows.
template<int WROWS, bool FUSED, bool GROUPED, int MODE>
__global__ void __launch_bounds__(256) mm_kernel(
    const float* __restrict__ A, const float* __restrict__ B1, const float* __restrict__ B3,
    float* __restrict__ C, const int* __restrict__ cnt, const int* __restrict__ tok,
    const float* __restrict__ wtv, int K, int ldc, int nrows,
    long long sAe, long long sBe, long long sCe)
{
    constexpr int WRN   = WROWS/32;
    constexpr int WCN   = 8/WRN;
    constexpr int NCOLS = FUSED ? 64 : 128;
    constexpr int NJ    = NCOLS/(WCN*8);
    constexpr int LDS   = 36;
    constexpr int AV    = WROWS/32;
    extern __shared__ float sm[];
    float* As = sm;
    float* Bs = sm + 2*WROWS*LDS;

    int e = GROUPED ? blockIdx.z : 0;
    int n = GROUPED ? cnt[e] : nrows;
    int rb = blockIdx.y*WROWS;
    if (rb >= n) return;
    int cb = blockIdx.x*NCOLS;
    if (GROUPED) {
        if (!FUSED) A += (size_t)e*sAe;
        B1 += (size_t)e*sBe;
        if (FUSED) B3 += (size_t)e*sBe;
        C += (size_t)e*sCe;
    }
    int t = threadIdx.x;
    int lane = t & 31, w = t >> 5;
    int wr = w / WCN, wc = w % WCN;
    int tq = lane >> 2, tr = lane & 3;

    const float* Ap[AV]; const float* Bp[4];
#pragma unroll
    for (int i = 0; i < AV; i++) {
        int lin = t + i*256;
        int row = lin >> 3, kq = (lin & 7) << 2;
        int ar = rb + row; if (GROUPED && ar > n-1) ar = n-1;
        if (GROUPED && FUSED) Ap[i] = A + (size_t)(tok[(size_t)e*NT + ar] >> 1)*K + kq;
        else                  Ap[i] = A + (size_t)ar*K + kq;
    }
#pragma unroll
    for (int i = 0; i < 4; i++) {
        int lin = t + i*256;
        int row = lin >> 3, kq = (lin & 7) << 2;
        if (!FUSED) Bp[i] = B1 + (size_t)(cb + row)*K + kq;
        else {
            const float* bb = (row < 64) ? B1 : B3;
            Bp[i] = bb + (size_t)(cb + (row & 63))*K + kq;
        }
    }
    uint32_t sA = s2u(As), sB = s2u(Bs);

    float acc1[2][NJ][4];
    float acc3[FUSED?2:1][NJ][4];
#pragma unroll
    for (int i = 0; i < 2; i++)
#pragma unroll
        for (int j = 0; j < NJ; j++)
#pragma unroll
            for (int q = 0; q < 4; q++) { acc1[i][j][q] = 0.f; if (FUSED) acc3[i][j][q] = 0.f; }

    auto load = [&](int c, int s){
#pragma unroll
        for (int i = 0; i < AV; i++) {
            int lin = t + i*256;
            int row = lin >> 3, kq = (lin & 7) << 2;
            cp16(sA + (uint32_t)(((s*WROWS + row)*LDS + kq)*4), Ap[i] + (size_t)c*32);
        }
#pragma unroll
        for (int i = 0; i < 4; i++) {
            int lin = t + i*256;
            int row = lin >> 3, kq = (lin & 7) << 2;
            cp16(sB + (uint32_t)(((s*128 + row)*LDS + kq)*4), Bp[i] + (size_t)c*32);
        }
        CP_COMMIT();
    };

    const int NC = K >> 5;
    load(0, 0);
    for (int c = 0; c < NC; c++) {
        int s = c & 1;
        if (c+1 < NC) { load(c+1, s^1); asm volatile("cp.async.wait_group 1;"); }
        else asm volatile("cp.async.wait_group 0;");
        __syncthreads();
        const float* Ab = As + (size_t)s*WROWS*LDS;
        const float* Bb = Bs + (size_t)s*128*LDS;
#pragma unroll
        for (int ks = 0; ks < 4; ks++) {
            int k0 = ks*8;
            uint32_t a[2][4];
#pragma unroll
            for (int i = 0; i < 2; i++) {
                int r0 = wr*32 + i*16;
                a[i][0] = fau(Ab[(r0+tq  )*LDS + k0+tr  ]);
                a[i][1] = fau(Ab[(r0+tq+8)*LDS + k0+tr  ]);
                a[i][2] = fau(Ab[(r0+tq  )*LDS + k0+tr+4]);
                a[i][3] = fau(Ab[(r0+tq+8)*LDS + k0+tr+4]);
            }
#pragma unroll
            for (int j = 0; j < NJ; j++) {
                int bc = wc*(NJ*8) + j*8 + tq;
                uint32_t b0 = fau(Bb[bc*LDS + k0+tr]);
                uint32_t b1 = fau(Bb[bc*LDS + k0+tr+4]);
#pragma unroll
                for (int i = 0; i < 2; i++) MMA8(acc1[i][j], a[i], b0, b1);
                if (FUSED) {
                    uint32_t c0 = fau(Bb[(bc+64)*LDS + k0+tr]);
                    uint32_t c1 = fau(Bb[(bc+64)*LDS + k0+tr+4]);
#pragma unroll
                    for (int i = 0; i < 2; i++) MMA8(acc3[i][j], a[i], c0, c1);
                }
            }
        }
        __syncthreads();
    }

    // -------- epilogue --------
#pragma unroll
    for (int i = 0; i < 2; i++)
#pragma unroll
        for (int hh = 0; hh < 2; hh++) {
            int gr = rb + wr*32 + i*16 + tq + hh*8;
            if (GROUPED && gr >= n) continue;
            int orow = gr; float wv = 1.f;
            if (GROUPED && MODE == 3) {
                int pk = tok[(size_t)e*NT + gr];
                wv   = wtv[(size_t)e*NT + gr];
                orow = pk >> 1;                        // token row
            }
            float* cr = C + (size_t)orow*ldc;
#pragma unroll
            for (int j = 0; j < NJ; j++) {
                int gc = cb + wc*(NJ*8) + j*8 + tr*2;
                float v0 = acc1[i][j][hh*2], v1 = acc1[i][j][hh*2+1];
                if (FUSED) {
                    float u0 = acc3[i][j][hh*2], u1 = acc3[i][j][hh*2+1];
                    float2 o;
                    o.x = to_tf32(v0/(1.f+__expf(-v0))*u0);
                    o.y = to_tf32(v1/(1.f+__expf(-v1))*u1);
                    *(float2*)(cr + gc) = o;
                } else if (MODE == 0) {
                    float2 o = {v0, v1};
                    *(float2*)(cr + gc) = o;
                } else if (MODE == 1) {
                    float2 o = *(float2*)(cr + gc);
                    o.x += v0; o.y += v1;
                    *(float2*)(cr + gc) = o;
                } else {                               // MODE 3: atomic scatter-add
                    atomicAdd(cr + gc,     wv*v0);
                    atomicAdd(cr + gc + 1, wv*v1);
                }
            }
        }
}

// ---------------- weight rounding fp32 -> RN tf32 ----------------------------
__global__ void round_copy(const float* __restrict__ s, float* __restrict__ d, int n4){
    int i = blockIdx.x*256 + threadIdx.x;
    if (i >= n4) return;
    float4 v = ((const float4*)s)[i];
    v.x=to_tf32(v.x); v.y=to_tf32(v.y); v.z=to_tf32(v.z); v.w=to_tf32(v.w);
    ((float4*)d)[i] = v;
}

// ---------------- rmsnorm ------------------------------------------------------
template<bool ROUND>
__global__ void rmsnorm_kernel(const float* __restrict__ in, const float* __restrict__ w,
                               float* __restrict__ out, float* __restrict__ out32){
    int row = blockIdx.x;
    const float* x = in + (size_t)row*Dd;
    float s = 0.f;
    for (int j = threadIdx.x; j < Dd; j += 256) { float v = x[j]; s += v*v; }
    __shared__ float red[8];
    for (int o = 16; o; o >>= 1) s += __shfl_xor_sync(0xffffffffu, s, o);
    if ((threadIdx.x & 31) == 0) red[threadIdx.x>>5] = s;
    __syncthreads();
    if (threadIdx.x < 8) {
        float v = red[threadIdx.x];
        for (int o = 4; o; o >>= 1) v += __shfl_xor_sync(0xffu, v, o);
        if (threadIdx.x == 0) red[0] = v;
    }
    __syncthreads();
    float rms = rsqrtf(red[0]/(float)Dd + 1e-5f);
    for (int j = threadIdx.x; j < Dd; j += 256) {
        float v = w[j]*x[j]*rms;
        out[(size_t)row*Dd+j] = ROUND ? to_tf32(v) : v;
        if (out32) out32[(size_t)row*Dd+j] = v;
    }
}

// ---------------- qkv split + RoPE (RN-tf32 outputs, Q pre-scaled) ------------
__global__ void split_rope_kernel(const float* __restrict__ qkv, float* __restrict__ Q,
                                  float* __restrict__ K, float* __restrict__ V){
    int idx = blockIdx.x*256 + threadIdx.x;
    if (idx >= NT*NHh*32) return;
    int d = idx & 31, h = (idx>>5)&7, bt = idx>>8;
    int tt = bt & (Tt-1), b = bt>>10;
    float inv = expf(-(float)d*0.28782313662425575f);
    float sn, cs; sincosf((float)tt*inv, &sn, &cs);
    size_t bi = (size_t)bt*1536 + h*64 + d;
    float q1=qkv[bi], q2=qkv[bi+32], k1=qkv[bi+512], k2=qkv[bi+544], v1=qkv[bi+1024], v2=qkv[bi+1056];
    size_t oi = ((size_t)(b*NHh+h)*Tt + tt)*64 + d;
    Q[oi]   =to_tf32((q1*cs-q2*sn)*0.125f); Q[oi+32]=to_tf32((q1*sn+q2*cs)*0.125f);
    K[oi]   =to_tf32(k1*cs-k2*sn);          K[oi+32]=to_tf32(k1*sn+k2*cs);
    V[oi]   =to_tf32(v1);                   V[oi+32]=to_tf32(v2);
}

// ---------------- tensor-core flash attention (causal, HD=64) -----------------
#define LDP 72
__global__ void __launch_bounds__(128) attn_tc_kernel(
    const float* __restrict__ Q, const float* __restrict__ K,
    const float* __restrict__ V, float* __restrict__ Out)
{
    extern __shared__ float sm[];
    float* Ks = sm;
    float* Vs = sm + 2*64*LDP;
    float* Ps = sm + 4*64*LDP;
    int bh = blockIdx.y;
    int t = threadIdx.x, lane = t & 31, w = t >> 5;
    int tq = lane >> 2, tr = lane & 3;
    const float* Qb = Q + (size_t)bh*Tt*64;
    const float* Kb = K + (size_t)bh*Tt*64;
    const float* Vb = V + (size_t)bh*Tt*64;
    int b = bh >> 3, hh = bh & 7;
    uint32_t sK = s2u(Ks), sV = s2u(Vs);

    auto load_kv = [&](int kt, int buf){
        const float* ks = Kb + (size_t)kt*64*64;
        const float* vs = Vb + (size_t)kt*64*64;
        uint32_t kd = sK + buf*64*LDP*4;
        uint32_t vd = sV + buf*64*LDP*4;
#pragma unroll
        for (int i = 0; i < 8; i++) {
            int u = t + i*128;
            int row = u >> 4, seg = u & 15;
            uint32_t off = (uint32_t)((row*LDP + seg*4)*4);
            cp16(kd + off, ks + row*64 + seg*4);
            cp16(vd + off, vs + row*64 + seg*4);
        }
        CP_COMMIT();
    };

    for (int pass = 0; pass < 2; pass++) {
        int qt = pass ? (15 - (int)blockIdx.x) : (int)blockIdx.x;
        int nkt = qt + 1;
        __syncthreads();
        load_kv(0, 0);
        for (int u = t; u < 64*16; u += 128) {
            int row = u >> 4, seg = u & 15;
            *(float4*)&Ps[row*LDP + seg*4] = *(const float4*)(Qb + (size_t)(qt*64+row)*64 + seg*4);
        }
        __syncthreads();
        uint32_t qa[8][4];
        int r0 = w*16 + tq;
#pragma unroll
        for (int ks = 0; ks < 8; ks++) {
            qa[ks][0] = fau(Ps[ r0   *LDP + ks*8+tr  ]);
            qa[ks][1] = fau(Ps[(r0+8)*LDP + ks*8+tr  ]);
            qa[ks][2] = fau(Ps[ r0   *LDP + ks*8+tr+4]);
            qa[ks][3] = fau(Ps[(r0+8)*LDP + ks*8+tr+4]);
        }
        float o[8][4];
#pragma unroll
        for (int j = 0; j < 8; j++)
#pragma unroll
            for (int q = 0; q < 4; q++) o[j][q] = 0.f;
        float m0 = -1e30f, m1 = -1e30f, l0 = 0.f, l1 = 0.f;

        for (int kt = 0; kt < nkt; kt++) {
            int buf = kt & 1;
            __syncthreads();
            if (kt+1 < nkt) { load_kv(kt+1, buf^1); asm volatile("cp.async.wait_group 1;"); }
            else asm volatile("cp.async.wait_group 0;");
            __syncthreads();

            const float* Kt = Ks + buf*64*LDP;
            const float* Vt = Vs + buf*64*LDP;
            float s[8][4];
#pragma unroll
            for (int j = 0; j < 8; j++)
#pragma unroll
                for (int q = 0; q < 4; q++) s[j][q] = 0.f;
#pragma unroll
            for (int nf = 0; nf < 8; nf++) {
#pragma unroll
                for (int ks = 0; ks < 8; ks++) {
                    uint32_t b0 = fau(Kt[(nf*8+tq)*LDP + ks*8+tr  ]);
                    uint32_t b1 = fau(Kt[(nf*8+tq)*LDP + ks*8+tr+4]);
                    MMA8(s[nf], qa[ks], b0, b1);
                }
            }
            if (kt == qt) {
                int qr0 = qt*64 + r0, qr1 = qr0 + 8;
#pragma unroll
                for (int nf = 0; nf < 8; nf++) {
                    int kc = kt*64 + nf*8 + 2*tr;
                    if (kc   > qr0) s[nf][0] = -1e30f;
                    if (kc+1 > qr0) s[nf][1] = -1e30f;
                    if (kc   > qr1) s[nf][2] = -1e30f;
                    if (kc+1 > qr1) s[nf][3] = -1e30f;
                }
            }
            float rm0 = -1e30f, rm1 = -1e30f;
#pragma unroll
            for (int nf = 0; nf < 8; nf++) {
                rm0 = fmaxf(rm0, fmaxf(s[nf][0], s[nf][1]));
                rm1 = fmaxf(rm1, fmaxf(s[nf][2], s[nf][3]));
            }
            rm0 = fmaxf(rm0, __shfl_xor_sync(0xffffffffu, rm0, 1));
            rm0 = fmaxf(rm0, __shfl_xor_sync(0xffffffffu, rm0, 2));
            rm1 = fmaxf(rm1, __shfl_xor_sync(0xffffffffu, rm1, 1));
            rm1 = fmaxf(rm1, __shfl_xor_sync(0xffffffffu, rm1, 2));
            float nm0 = fmaxf(m0, rm0), nm1 = fmaxf(m1, rm1);
            float f0 = __expf(m0 - nm0), f1 = __expf(m1 - nm1);
            float rs0 = 0.f, rs1 = 0.f;
#pragma unroll
            for (int nf = 0; nf < 8; nf++) {
                float p0 = __expf(s[nf][0] - nm0);
                float p1 = __expf(s[nf][1] - nm0);
                float p2 = __expf(s[nf][2] - nm1);
                float p3 = __expf(s[nf][3] - nm1);
                rs0 += p0 + p1; rs1 += p2 + p3;
                Ps[ r0   *LDP + nf*8 + 2*tr    ] = to_tf32(p0);
                Ps[ r0   *LDP + nf*8 + 2*tr + 1] = to_tf32(p1);
                Ps[(r0+8)*LDP + nf*8 + 2*tr    ] = to_tf32(p2);
                Ps[(r0+8)*LDP + nf*8 + 2*tr + 1] = to_tf32(p3);
            }
            rs0 += __shfl_xor_sync(0xffffffffu, rs0, 1);
            rs0 += __shfl_xor_sync(0xffffffffu, rs0, 2);
            rs1 += __shfl_xor_sync(0xffffffffu, rs1, 1);
            rs1 += __shfl_xor_sync(0xffffffffu, rs1, 2);
            l0 = l0*f0 + rs0; m0 = nm0;
            l1 = l1*f1 + rs1; m1 = nm1;
#pragma unroll
            for (int j = 0; j < 8; j++) { o[j][0]*=f0; o[j][1]*=f0; o[j][2]*=f1; o[j][3]*=f1; }
            __syncwarp();
            uint32_t pa[8][4];
#pragma unroll
            for (int ks = 0; ks < 8; ks++) {
                pa[ks][0] = fau(Ps[ r0   *LDP + ks*8+tr  ]);
                pa[ks][1] = fau(Ps[(r0+8)*LDP + ks*8+tr  ]);
                pa[ks][2] = fau(Ps[ r0   *LDP + ks*8+tr+4]);
                pa[ks][3] = fau(Ps[(r0+8)*LDP + ks*8+tr+4]);
            }
#pragma unroll
            for (int nf = 0; nf < 8; nf++) {
#pragma unroll
                for (int ks = 0; ks < 8; ks++) {
                    uint32_t b0 = fau(Vt[(ks*8+tr  )*LDP + nf*8+tq]);
                    uint32_t b1 = fau(Vt[(ks*8+tr+4)*LDP + nf*8+tq]);
                    MMA8(o[nf], pa[ks], b0, b1);
                }
            }
        }
        float il0 = 1.f/l0, il1 = 1.f/l1;
        int qr = qt*64 + r0;
        float* o0 = Out + ((size_t)(b*Tt + qr    ))*Dd + hh*64;
        float* o1 = Out + ((size_t)(b*Tt + qr + 8))*Dd + hh*64;
#pragma unroll
        for (int nf = 0; nf < 8; nf++) {
            int gc = nf*8 + 2*tr;
            float2 a = { to_tf32(o[nf][0]*il0), to_tf32(o[nf][1]*il0) };
            float2 c = { to_tf32(o[nf][2]*il1), to_tf32(o[nf][3]*il1) };
            *(float2*)(o0 + gc) = a;
            *(float2*)(o1 + gc) = c;
        }
    }
}

// ---------------- router (fp32, unrounded input) ------------------------------
__global__ void router_kernel(const float* __restrict__ X, const float* __restrict__ RW,
                              int* __restrict__ cnt, int* __restrict__ tok, float* __restrict__ wt){
    int g = blockIdx.x*blockDim.x + threadIdx.x;
    int warp = g>>5, lane = g&31;
    if (warp >= NT) return;
    const float* xr = X + (size_t)warp*Dd;
    float lg[Ee];
#pragma unroll
    for (int e = 0; e < Ee; e++) {
        const float* w = RW + (size_t)e*Dd;
        float s = 0.f;
        for (int j = lane; j < Dd; j += 32) s += xr[j]*w[j];
        for (int o = 16; o; o >>= 1) s += __shfl_xor_sync(0xffffffffu, s, o);
        lg[e] = s;
    }
    if (lane == 0) {
        int i0 = 0; float v0 = lg[0];
#pragma unroll
        for (int e = 1; e < Ee; e++) if (lg[e] > v0) { v0 = lg[e]; i0 = e; }
        int i1 = -1; float v1 = -3.4e38f;
#pragma unroll
        for (int e = 0; e < Ee; e++) if (e != i0 && lg[e] > v1) { v1 = lg[e]; i1 = e; }
        float e1 = expf(v1 - v0);
        float w0 = 1.f/(1.f+e1), w1 = e1/(1.f+e1);
        int p0 = atomicAdd(&cnt[i0], 1);
        tok[i0*NT+p0] = warp*2;   wt[i0*NT+p0] = w0;
        int p1 = atomicAdd(&cnt[i1], 1);
        tok[i1*NT+p1] = warp*2+1; wt[i1*NT+p1] = w1;
    }
}

// ---------------- host orchestration ------------------------------------------
extern "C" void kernel_launch(void* const* d_in, const int* in_sizes, int n_in,
                              void* d_out, int out_size) {
    (void)in_sizes; (void)n_in; (void)out_size;
    const float* x        = (const float*)d_in[0];
    const float* qkv_w    = (const float*)d_in[1];
    const float* out_w    = (const float*)d_in[2];
    const float* norm1_w  = (const float*)d_in[3];
    const float* norm2_w  = (const float*)d_in[4];
    const float* router_w = (const float*)d_in[5];
    const float* moe_w1   = (const float*)d_in[6];
    const float* moe_w2   = (const float*)d_in[7];
    const float* moe_w3   = (const float*)d_in[8];
    const float* f_w1     = (const float*)d_in[9];
    const float* f_w2     = (const float*)d_in[10];
    const float* f_w3     = (const float*)d_in[11];
    const float* norm_f   = (const float*)d_in[12];
    float* out = (float*)d_out;

    float *h,*xn,*xn32,*qkv,*q,*k,*v,*attn,*hbuf,*wt,*wr;
    int *cnt,*tok;
    cudaGetSymbolAddress((void**)&h, g_h);       cudaGetSymbolAddress((void**)&xn, g_xn);
    cudaGetSymbolAddress((void**)&xn32, g_xn32); cudaGetSymbolAddress((void**)&qkv, g_qkv);
    cudaGetSymbolAddress((void**)&q, g_q);       cudaGetSymbolAddress((void**)&k, g_k);
    cudaGetSymbolAddress((void**)&v, g_v);       cudaGetSymbolAddress((void**)&attn, g_attn);
    cudaGetSymbolAddress((void**)&hbuf, g_hbuf);
    cudaGetSymbolAddress((void**)&wr, g_wr);     cudaGetSymbolAddress((void**)&cnt, g_cnt);
    cudaGetSymbolAddress((void**)&tok, g_tok);   cudaGetSymbolAddress((void**)&wt, g_wt);

    // one-time host resources (host-side only; captured work identical every call)
    static cudaStream_t s1 = nullptr;
    static cudaEvent_t evF = nullptr, evJ0 = nullptr, evJ1 = nullptr, evJ2 = nullptr;
    if (!s1) {
        cudaStreamCreateWithFlags(&s1, cudaStreamNonBlocking);
        cudaEventCreateWithFlags(&evF,  cudaEventDisableTiming);
        cudaEventCreateWithFlags(&evJ0, cudaEventDisableTiming);
        cudaEventCreateWithFlags(&evJ1, cudaEventDisableTiming);
        cudaEventCreateWithFlags(&evJ2, cudaEventDisableTiming);
    }

    const int attn_smem = 5*64*LDP*sizeof(float);
    cudaFuncSetAttribute(attn_tc_kernel, cudaFuncAttributeMaxDynamicSharedMemorySize, attn_smem);
    const int SM64  = (2*64*36 + 2*128*36)*4;
    const int SM128 = (2*128*36 + 2*128*36)*4;
    cudaFuncSetAttribute(mm_kernel<64 ,false,false,0>, cudaFuncAttributeMaxDynamicSharedMemorySize, SM64);
    cudaFuncSetAttribute(mm_kernel<64 ,false,false,1>, cudaFuncAttributeMaxDynamicSharedMemorySize, SM64);
    cudaFuncSetAttribute(mm_kernel<64 ,false,true ,3>, cudaFuncAttributeMaxDynamicSharedMemorySize, SM64);
    cudaFuncSetAttribute(mm_kernel<128,true ,false,0>, cudaFuncAttributeMaxDynamicSharedMemorySize, SM128);
    cudaFuncSetAttribute(mm_kernel<128,true ,true ,0>, cudaFuncAttributeMaxDynamicSharedMemorySize, SM128);

    // ---- fork: big weight rounding on s1, ordered by first use --------------
    cudaEventRecord(evF, 0);
    cudaStreamWaitEvent(s1, evF, 0);
    #define RC(st, src, dstoff, nfl) \
        round_copy<<<(int)(((nfl)/4+255)/256),256,0,st>>>((src), wr+(dstoff), (int)((nfl)/4))
    // layer-0 MoE weights (m = 0)
    RC(s1, moe_w1,            OFF_MW1,        SZ_MW1);
    RC(s1, moe_w3,            OFF_MW3,        SZ_MW1);
    RC(s1, moe_w2,            OFF_MW2,        SZ_MW1);
    cudaEventRecord(evJ0, s1);
    // dense FFN weights (both m)
    RC(s1, f_w1, OFF_FW1, SZ_FW);
    RC(s1, f_w3, OFF_FW3, SZ_FW);
    RC(s1, f_w2, OFF_FW2, SZ_FW);
    cudaEventRecord(evJ1, s1);
    // layer-2 MoE weights (m = 1)
    RC(s1, moe_w1+SZ_MW1,     OFF_MW1+SZ_MW1, SZ_MW1);
    RC(s1, moe_w3+SZ_MW1,     OFF_MW3+SZ_MW1, SZ_MW1);
    RC(s1, moe_w2+SZ_MW1,     OFF_MW2+SZ_MW1, SZ_MW1);
    cudaEventRecord(evJ2, s1);

    // ---- main stream: small weights + layers --------------------------------
    RC((cudaStream_t)0, qkv_w, OFF_QKV, SZ_QKV);
    RC((cudaStream_t)0, out_w, OFF_OUT, SZ_OUT);
    cudaMemcpyAsync(h, x, (size_t)NT*Dd*sizeof(float), cudaMemcpyDeviceToDevice, 0);

    for (int l = 0; l < Ll; l++) {
        rmsnorm_kernel<true><<<NT,256>>>(h, norm1_w+(size_t)l*Dd, xn, nullptr);
        mm_kernel<64,false,false,0><<<dim3(12,32),256,SM64>>>(
            xn, wr+OFF_QKV+(size_t)l*1536*Dd, nullptr, qkv,
            nullptr,nullptr,nullptr, Dd, 1536, NT, 0,0,0);
        split_rope_kernel<<<(NT*NHh*32+255)/256,256>>>(qkv, q, k, v);
        attn_tc_kernel<<<dim3(8, Bz*NHh),128,attn_smem>>>(q, k, v, attn);
        mm_kernel<64,false,false,1><<<dim3(4,32),256,SM64>>>(
            attn, wr+OFF_OUT+(size_t)l*Dd*Dd, nullptr, h,
            nullptr,nullptr,nullptr, Dd, Dd, NT, 0,0,0);

        if (l == 0 || l == 2) {
            int m = l/2;
            rmsnorm_kernel<true><<<NT,256>>>(h, norm2_w+(size_t)l*Dd, xn, xn32);
            cudaMemsetAsync(cnt, 0, Ee*sizeof(int), 0);
            router_kernel<<<(NT*32+127)/128,128>>>(xn32, router_w+(size_t)m*Ee*Dd, cnt, tok, wt);
            cudaStreamWaitEvent((cudaStream_t)0, m == 0 ? evJ0 : evJ2, 0);
            mm_kernel<128,true,true,0><<<dim3(Hh/64,16,Ee),256,SM128>>>(
                xn, wr+OFF_MW1+(size_t)m*SZ_MW1, wr+OFF_MW3+(size_t)m*SZ_MW1, hbuf,
                cnt, tok, nullptr, Dd, Hh, 0, 0, (long long)Hh*Dd, (long long)NT*Hh);
            mm_kernel<64,false,true,3><<<dim3(4,32,Ee),256,SM64>>>(
                hbuf, wr+OFF_MW2+(size_t)m*SZ_MW1, nullptr, h,
                cnt, tok, wt, Hh, Dd, 0, (long long)NT*Hh, (long long)Dd*Hh, 0);
        } else {
            int m = (l == 1) ? 0 : 1;
            rmsnorm_kernel<true><<<NT,256>>>(h, norm2_w+(size_t)l*Dd, xn, nullptr);
            if (l == 1) cudaStreamWaitEvent((cudaStream_t)0, evJ1, 0);
            mm_kernel<128,true,false,0><<<dim3(Hh/64,16),256,SM128>>>(
                xn, wr+OFF_FW1+(size_t)m*Hh*Dd, wr+OFF_FW3+(size_t)m*Hh*Dd, hbuf,
                nullptr,nullptr,nullptr, Dd, Hh, NT, 0,0,0);
            mm_kernel<64,false,false,1><<<dim3(4,32),256,SM64>>>(
                hbuf, wr+OFF_FW2+(size_t)m*Dd*Hh, nullptr, h,
                nullptr,nullptr,nullptr, Hh, Dd, NT, 0,0,0);
        }
    }
    rmsnorm_kernel<false><<<NT,256>>>(h, norm_f, out, nullptr);
}